// round 1
// baseline (speedup 1.0000x reference)
#include <cuda_runtime.h>
#include <cstdint>

// Problem constants
constexpr int B_  = 4;
constexpr int S_  = 2048;
constexpr int D_  = 1024;
constexpr int H_  = 16;
constexpr int DH_ = 64;
constexpr int M_TOT = B_ * S_;   // 8192
constexpr int K_DIM = D_;        // 1024

// Scratch (device globals: allocation-free rule)
__device__ float g_q[B_ * H_ * S_ * DH_];
__device__ float g_k[B_ * H_ * S_ * DH_];
__device__ float g_v[B_ * H_ * S_ * DH_];
__device__ float g_att[M_TOT * D_];
__device__ float g_cos[S_ * (DH_ / 2)];
__device__ float g_sin[S_ * (DH_ / 2)];

// Packed fp32x2 FMA (Blackwell): two IEEE fp32 FMAs per instruction.
__device__ __forceinline__ float2 ffma2(float2 a, float2 b, float2 c) {
    float2 d;
    asm("fma.rn.f32x2 %0, %1, %2, %3;"
        : "=l"(*reinterpret_cast<unsigned long long*>(&d))
        : "l"(*reinterpret_cast<unsigned long long*>(&a)),
          "l"(*reinterpret_cast<unsigned long long*>(&b)),
          "l"(*reinterpret_cast<unsigned long long*>(&c)));
    return d;
}

// ---------------------------------------------------------------------------
// SGEMM: C[m,n] = sum_k A[m,k] * W[n,k]    (A: [8192,1024], W: [1024,1024])
// 128x128 tile, BK=8, 256 threads, 8x8 per thread (as 8x4 float2).
// mode 0: C[m*1024+n] plain.
// mode 1: scatter to heads layout dst[((b*16+h)*2048+s)*64+dh], h=n/64, dh=n%64.
// ---------------------------------------------------------------------------
__global__ __launch_bounds__(256, 2)
void sgemm128(const float* __restrict__ A, const float* __restrict__ W,
              float* __restrict__ Dst, int mode)
{
    __shared__ __align__(16) float As[8][128];
    __shared__ __align__(16) float Bs[8][128];

    const int tid = threadIdx.x;
    const int tx = tid & 15, ty = tid >> 4;
    const int m0 = blockIdx.y * 128, n0 = blockIdx.x * 128;

    const int lrow = tid >> 1;          // 0..127
    const int lcol = (tid & 1) << 2;    // 0 or 4
    const float* Ap = A + (m0 + lrow) * K_DIM + lcol;
    const float* Wp = W + (n0 + lrow) * K_DIM + lcol;

    float2 c[8][4];
#pragma unroll
    for (int i = 0; i < 8; i++)
#pragma unroll
        for (int j = 0; j < 4; j++) c[i][j] = make_float2(0.f, 0.f);

    for (int kt = 0; kt < K_DIM; kt += 8) {
        float4 av = *reinterpret_cast<const float4*>(Ap + kt);
        float4 wv = *reinterpret_cast<const float4*>(Wp + kt);
        __syncthreads();
        As[lcol + 0][lrow] = av.x; As[lcol + 1][lrow] = av.y;
        As[lcol + 2][lrow] = av.z; As[lcol + 3][lrow] = av.w;
        Bs[lcol + 0][lrow] = wv.x; Bs[lcol + 1][lrow] = wv.y;
        Bs[lcol + 2][lrow] = wv.z; Bs[lcol + 3][lrow] = wv.w;
        __syncthreads();
#pragma unroll
        for (int k = 0; k < 8; k++) {
            float4 a0 = *reinterpret_cast<const float4*>(&As[k][ty * 8]);
            float4 a1 = *reinterpret_cast<const float4*>(&As[k][ty * 8 + 4]);
            float4 b0 = *reinterpret_cast<const float4*>(&Bs[k][tx * 8]);
            float4 b1 = *reinterpret_cast<const float4*>(&Bs[k][tx * 8 + 4]);
            float  a[8]  = {a0.x, a0.y, a0.z, a0.w, a1.x, a1.y, a1.z, a1.w};
            float2 bb[4] = {make_float2(b0.x, b0.y), make_float2(b0.z, b0.w),
                            make_float2(b1.x, b1.y), make_float2(b1.z, b1.w)};
#pragma unroll
            for (int i = 0; i < 8; i++) {
                float2 aa = make_float2(a[i], a[i]);
#pragma unroll
                for (int jj = 0; jj < 4; jj++) c[i][jj] = ffma2(aa, bb[jj], c[i][jj]);
            }
        }
    }

    if (mode == 0) {
#pragma unroll
        for (int i = 0; i < 8; i++) {
            int m = m0 + ty * 8 + i;
            float* dst = Dst + m * 1024 + n0 + tx * 8;
            *reinterpret_cast<float4*>(dst) =
                make_float4(c[i][0].x, c[i][0].y, c[i][1].x, c[i][1].y);
            *reinterpret_cast<float4*>(dst + 4) =
                make_float4(c[i][2].x, c[i][2].y, c[i][3].x, c[i][3].y);
        }
    } else {
        int n  = n0 + tx * 8;
        int h  = n >> 6;
        int dh = n & 63;
#pragma unroll
        for (int i = 0; i < 8; i++) {
            int m = m0 + ty * 8 + i;
            int b = m >> 11, s = m & 2047;
            float* dst = Dst + (((b << 4) + h) * S_ + s) * DH_ + dh;
            *reinterpret_cast<float4*>(dst) =
                make_float4(c[i][0].x, c[i][0].y, c[i][1].x, c[i][1].y);
            *reinterpret_cast<float4*>(dst + 4) =
                make_float4(c[i][2].x, c[i][2].y, c[i][3].x, c[i][3].y);
        }
    }
}

// ---------------------------------------------------------------------------
// RoPE cos/sin table: 2048 positions x 32 freqs, double-precision angles
// (fp32-rounded angle to track the reference's fp32 computation).
// ---------------------------------------------------------------------------
__global__ void rope_table_kernel()
{
    int idx = blockIdx.x * 256 + threadIdx.x;   // 65536
    int s = idx >> 5, i = idx & 31;
    double inv = exp(-((double)(2 * i) / 64.0) * log(10000.0));
    float  angf = (float)s * (float)inv;        // fp32 angle, like the reference
    double ang  = (double)angf;
    g_cos[idx] = (float)cos(ang);
    g_sin[idx] = (float)sin(ang);
}

// In-place interleaved RoPE on [bh][s][dh] tensor. One thread per (even,odd) pair.
__global__ void rope_kernel(float* __restrict__ t)
{
    int idx = blockIdx.x * 256 + threadIdx.x;   // 64*2048*32 = 4194304
    int i = idx & 31;
    int s = (idx >> 5) & 2047;
    float cv = g_cos[s * 32 + i];
    float sv = g_sin[s * 32 + i];
    float2* p = reinterpret_cast<float2*>(t);
    float2 x = p[idx];                           // element offset 2*idx == (bh*2048+s)*64 + 2i
    p[idx] = make_float2(x.x * cv - x.y * sv, x.x * sv + x.y * cv);
}

// ---------------------------------------------------------------------------
// Causal flash attention, fp32, 64x64 tiles, DH=64.
// grid = (32 q-tiles, 64 bh), 256 threads. Each thread: 4 rows x 4 cols.
// Qt/Kt stored [dh][row] (transposed) for conflict-light LDS; Ps reuses Kt smem.
// ---------------------------------------------------------------------------
__global__ __launch_bounds__(256, 2)
void fattn_kernel(const float* __restrict__ Q, const float* __restrict__ Kt_g,
                  const float* __restrict__ V, float* __restrict__ att)
{
    __shared__ __align__(16) float Qt[64][64];    // [dh][r]
    __shared__ __align__(16) float KtPs[64][64];  // Kt: [dh][c] during S; Ps: [r][k] after
    __shared__ __align__(16) float Vs[64][64];    // [k][d]

    const int tid = threadIdx.x, tx = tid & 15, ty = tid >> 4;
    const int qi = gridDim.x - 1 - blockIdx.x;    // heavy tiles first
    const int bh = blockIdx.y;

    const float* qb = Q + ((size_t)bh * S_ + qi * 64) * 64;
#pragma unroll
    for (int it = 0; it < 4; it++) {
        int idx = tid + it * 256;
        int r = idx >> 4, c4 = (idx & 15) << 2;
        float4 tq = *reinterpret_cast<const float4*>(qb + r * 64 + c4);
        Qt[c4 + 0][r] = tq.x; Qt[c4 + 1][r] = tq.y;
        Qt[c4 + 2][r] = tq.z; Qt[c4 + 3][r] = tq.w;
    }

    float2 o[4][2];
    float  mi[4], li[4];
#pragma unroll
    for (int i = 0; i < 4; i++) {
        o[i][0] = o[i][1] = make_float2(0.f, 0.f);
        mi[i] = -1e30f; li[i] = 0.f;
    }

    for (int j = 0; j <= qi; j++) {
        const float* kb = Kt_g + ((size_t)bh * S_ + j * 64) * 64;
        const float* vb = V    + ((size_t)bh * S_ + j * 64) * 64;
        __syncthreads();   // previous iteration's Ps/Vs reads complete (also covers Qt on j==0)
#pragma unroll
        for (int it = 0; it < 4; it++) {
            int idx = tid + it * 256;
            int r = idx >> 4, c4 = (idx & 15) << 2;
            float4 tk = *reinterpret_cast<const float4*>(kb + r * 64 + c4);
            KtPs[c4 + 0][r] = tk.x; KtPs[c4 + 1][r] = tk.y;
            KtPs[c4 + 2][r] = tk.z; KtPs[c4 + 3][r] = tk.w;
            float4 tv = *reinterpret_cast<const float4*>(vb + r * 64 + c4);
            *reinterpret_cast<float4*>(&Vs[r][c4]) = tv;
        }
        __syncthreads();

        // S = Q K^T (rows ty*4.., cols tx*4..)
        float2 s2[4][2];
#pragma unroll
        for (int i = 0; i < 4; i++) s2[i][0] = s2[i][1] = make_float2(0.f, 0.f);
#pragma unroll 16
        for (int d = 0; d < 64; d++) {
            float4 aq = *reinterpret_cast<const float4*>(&Qt[d][ty * 4]);
            float4 bk = *reinterpret_cast<const float4*>(&KtPs[d][tx * 4]);
            float  aqv[4] = {aq.x, aq.y, aq.z, aq.w};
            float2 bkv[2] = {make_float2(bk.x, bk.y), make_float2(bk.z, bk.w)};
#pragma unroll
            for (int i = 0; i < 4; i++) {
                float2 aa = make_float2(aqv[i], aqv[i]);
                s2[i][0] = ffma2(aa, bkv[0], s2[i][0]);
                s2[i][1] = ffma2(aa, bkv[1], s2[i][1]);
            }
        }
        __syncthreads();   // all threads done reading Kt; smem becomes Ps

        float sv[4][4];
#pragma unroll
        for (int i = 0; i < 4; i++) {
            sv[i][0] = s2[i][0].x * 0.125f; sv[i][1] = s2[i][0].y * 0.125f;
            sv[i][2] = s2[i][1].x * 0.125f; sv[i][3] = s2[i][1].y * 0.125f;
        }
        if (j == qi) {
#pragma unroll
            for (int i = 0; i < 4; i++)
#pragma unroll
                for (int jj = 0; jj < 4; jj++)
                    if (tx * 4 + jj > ty * 4 + i) sv[i][jj] = -1e30f;
        }

#pragma unroll
        for (int i = 0; i < 4; i++) {
            float rm = fmaxf(fmaxf(sv[i][0], sv[i][1]), fmaxf(sv[i][2], sv[i][3]));
#pragma unroll
            for (int off = 1; off < 16; off <<= 1)
                rm = fmaxf(rm, __shfl_xor_sync(0xffffffffu, rm, off));
            float mn = fmaxf(mi[i], rm);
            float al = __expf(mi[i] - mn);
            mi[i] = mn;
            li[i] *= al;
            o[i][0].x *= al; o[i][0].y *= al; o[i][1].x *= al; o[i][1].y *= al;
            float p0 = __expf(sv[i][0] - mn), p1 = __expf(sv[i][1] - mn);
            float p2 = __expf(sv[i][2] - mn), p3 = __expf(sv[i][3] - mn);
            float rs = p0 + p1 + p2 + p3;
#pragma unroll
            for (int off = 1; off < 16; off <<= 1)
                rs += __shfl_xor_sync(0xffffffffu, rs, off);
            li[i] += rs;
            *reinterpret_cast<float4*>(&KtPs[ty * 4 + i][tx * 4]) = make_float4(p0, p1, p2, p3);
        }
        __syncthreads();

        // O += P @ V
#pragma unroll 16
        for (int kk = 0; kk < 64; kk++) {
            float4 vv = *reinterpret_cast<const float4*>(&Vs[kk][tx * 4]);
            float2 v2[2] = {make_float2(vv.x, vv.y), make_float2(vv.z, vv.w)};
#pragma unroll
            for (int i = 0; i < 4; i++) {
                float pr = KtPs[ty * 4 + i][kk];
                float2 aa = make_float2(pr, pr);
                o[i][0] = ffma2(aa, v2[0], o[i][0]);
                o[i][1] = ffma2(aa, v2[1], o[i][1]);
            }
        }
    }

    const int b = bh >> 4, h = bh & 15;
#pragma unroll
    for (int i = 0; i < 4; i++) {
        float inv = 1.0f / li[i];
        int s = qi * 64 + ty * 4 + i;
        float* dst = att + ((size_t)(b * S_ + s)) * D_ + h * 64 + tx * 4;
        *reinterpret_cast<float4*>(dst) =
            make_float4(o[i][0].x * inv, o[i][0].y * inv, o[i][1].x * inv, o[i][1].y * inv);
    }
}

// ---------------------------------------------------------------------------
extern "C" void kernel_launch(void* const* d_in, const int* in_sizes, int n_in,
                              void* d_out, int out_size)
{
    (void)in_sizes; (void)n_in; (void)out_size;
    const float* x  = (const float*)d_in[0];
    const float* wq = (const float*)d_in[1];
    const float* wk = (const float*)d_in[2];
    const float* wv = (const float*)d_in[3];
    const float* wo = (const float*)d_in[4];
    float* out = (float*)d_out;

    float *pq, *pk, *pv, *patt;
    cudaGetSymbolAddress((void**)&pq,   g_q);
    cudaGetSymbolAddress((void**)&pk,   g_k);
    cudaGetSymbolAddress((void**)&pv,   g_v);
    cudaGetSymbolAddress((void**)&patt, g_att);

    dim3 gg(D_ / 128, M_TOT / 128);   // (8, 64)
    sgemm128<<<gg, 256>>>(x, wq, pq, 1);
    sgemm128<<<gg, 256>>>(x, wk, pk, 1);
    sgemm128<<<gg, 256>>>(x, wv, pv, 1);

    rope_table_kernel<<<(S_ * 32) / 256, 256>>>();
    rope_kernel<<<(B_ * H_ * S_ * 32) / 256, 256>>>(pq);
    rope_kernel<<<(B_ * H_ * S_ * 32) / 256, 256>>>(pk);

    fattn_kernel<<<dim3(S_ / 64, B_ * H_), 256>>>(pq, pk, pv, patt);

    sgemm128<<<gg, 256>>>(patt, wo, out, 0);
}

// round 3
// speedup vs baseline: 1.7977x; 1.7977x over previous
#include <cuda_runtime.h>
#include <cuda_bf16.h>
#include <cstdint>

// ---------------------------------------------------------------------------
// Problem constants
// ---------------------------------------------------------------------------
constexpr int B_  = 4;
constexpr int S_  = 2048;
constexpr int D_  = 1024;
constexpr int H_  = 16;
constexpr int DH_ = 64;
constexpr int M_TOT = B_ * S_;                    // 8192
constexpr size_t QKV_STRIDE = (size_t)M_TOT * D_; // 8388608 floats
constexpr size_t W_STRIDE   = (size_t)D_ * D_;    // 1048576

// Scratch (device globals: allocation-free rule)
__device__ float g_qkv[3 * M_TOT * D_];           // q | k | v, each [8192][1024]
__device__ float g_att[M_TOT * D_];
__device__ float g_cos[S_ * (DH_ / 2)];
__device__ float g_sin[S_ * (DH_ / 2)];
__device__ __nv_bfloat16 g_ah[M_TOT * D_];        // hi split of activation
__device__ __nv_bfloat16 g_al[M_TOT * D_];        // lo split of activation
__device__ __nv_bfloat16 g_wh[4 * W_STRIDE];      // hi split of wq|wk|wv|wo
__device__ __nv_bfloat16 g_wl[4 * W_STRIDE];      // lo split

// ---------------------------------------------------------------------------
// helpers
// ---------------------------------------------------------------------------
__device__ __forceinline__ uint32_t smem_to_u32(const void* smem_ptr) {
    uint32_t addr;
    asm("{ .reg .u64 tmp; cvta.to.shared.u64 tmp, %1; cvt.u32.u64 %0, tmp; }"
        : "=r"(addr) : "l"(smem_ptr));
    return addr;
}

__device__ __forceinline__ void cp_async16(uint32_t saddr, const void* gptr) {
    asm volatile("cp.async.cg.shared.global [%0], [%1], 16;"
                 :: "r"(saddr), "l"(gptr) : "memory");
}
__device__ __forceinline__ void cp_commit() {
    asm volatile("cp.async.commit_group;" ::: "memory");
}
__device__ __forceinline__ void cp_wait0() {
    asm volatile("cp.async.wait_group 0;" ::: "memory");
}

__device__ __forceinline__ void ldmx4(uint32_t* r, uint32_t addr) {
    asm volatile("ldmatrix.sync.aligned.m8n8.x4.shared.b16 {%0,%1,%2,%3}, [%4];"
                 : "=r"(r[0]), "=r"(r[1]), "=r"(r[2]), "=r"(r[3]) : "r"(addr));
}

__device__ __forceinline__ void mma_bf16(float* c, const uint32_t* a,
                                         uint32_t b0, uint32_t b1) {
    asm volatile(
        "mma.sync.aligned.m16n8k16.row.col.f32.bf16.bf16.f32 "
        "{%0,%1,%2,%3}, {%4,%5,%6,%7}, {%8,%9}, {%0,%1,%2,%3};"
        : "+f"(c[0]), "+f"(c[1]), "+f"(c[2]), "+f"(c[3])
        : "r"(a[0]), "r"(a[1]), "r"(a[2]), "r"(a[3]), "r"(b0), "r"(b1));
}

// Packed fp32x2 FMA (Blackwell) for the SIMT attention kernel
__device__ __forceinline__ float2 ffma2(float2 a, float2 b, float2 c) {
    float2 d;
    asm("fma.rn.f32x2 %0, %1, %2, %3;"
        : "=l"(*reinterpret_cast<unsigned long long*>(&d))
        : "l"(*reinterpret_cast<unsigned long long*>(&a)),
          "l"(*reinterpret_cast<unsigned long long*>(&b)),
          "l"(*reinterpret_cast<unsigned long long*>(&c)));
    return d;
}

// ---------------------------------------------------------------------------
// Split fp32 -> (hi, lo) bf16.  x = hi + lo + O(2^-18 x)
// ---------------------------------------------------------------------------
__device__ __forceinline__ uint32_t pack2bf(__nv_bfloat16 a, __nv_bfloat16 b) {
    return (uint32_t)__bfloat16_as_ushort(a) | ((uint32_t)__bfloat16_as_ushort(b) << 16);
}

__global__ void split_kernel(const float* __restrict__ src,
                             __nv_bfloat16* __restrict__ hi,
                             __nv_bfloat16* __restrict__ lo, int n4)
{
    int i = blockIdx.x * 256 + threadIdx.x;
    if (i >= n4) return;
    float4 v = reinterpret_cast<const float4*>(src)[i];
    __nv_bfloat16 h0 = __float2bfloat16(v.x), h1 = __float2bfloat16(v.y);
    __nv_bfloat16 h2 = __float2bfloat16(v.z), h3 = __float2bfloat16(v.w);
    __nv_bfloat16 l0 = __float2bfloat16(v.x - __bfloat162float(h0));
    __nv_bfloat16 l1 = __float2bfloat16(v.y - __bfloat162float(h1));
    __nv_bfloat16 l2 = __float2bfloat16(v.z - __bfloat162float(h2));
    __nv_bfloat16 l3 = __float2bfloat16(v.w - __bfloat162float(h3));
    reinterpret_cast<uint2*>(hi)[i] = make_uint2(pack2bf(h0, h1), pack2bf(h2, h3));
    reinterpret_cast<uint2*>(lo)[i] = make_uint2(pack2bf(l0, l1), pack2bf(l2, l3));
}

// ---------------------------------------------------------------------------
// bf16 mma.sync GEMM with 3-term fp32 emulation.
// C[m,n] = sum_k A[m,k]*W[n,k], A:[8192,1024] W:[1024,1024] (both split hi/lo).
// 48 k64-steps: seg0 Ah*Wh, seg1 Al*Wh, seg2 Ah*Wl.  BM=BN=128, BK=64.
// 256 threads = 8 warps (4m x 2n), warp tile 32x64. Double-buffered cp.async.
// grid.z selects weight (z*W_STRIDE) and dst (z*dstride).
// ---------------------------------------------------------------------------
constexpr int GEMM_SMEM = 65536;   // 2 stages * (16KB A + 16KB B)

__global__ void __launch_bounds__(256)
gemm_bf3(const __nv_bfloat16* __restrict__ Ah, const __nv_bfloat16* __restrict__ Al,
         const __nv_bfloat16* __restrict__ Wh, const __nv_bfloat16* __restrict__ Wl,
         float* __restrict__ Dst, size_t dstride)
{
    extern __shared__ char smem[];
    const uint32_t sb = smem_to_u32(smem);
    const int tid = threadIdx.x, lane = tid & 31, wid = tid >> 5;
    const int z = blockIdx.z;
    const __nv_bfloat16* WhZ = Wh + (size_t)z * W_STRIDE;
    const __nv_bfloat16* WlZ = Wl + (size_t)z * W_STRIDE;
    float* D = Dst + (size_t)z * dstride;
    const int m0 = blockIdx.y * 128, n0 = blockIdx.x * 128;
    const int wm = (wid >> 1) * 32, wn = (wid & 1) * 64;

    // per-thread load slots: 1024 chunks (16B) per operand tile, 4 per thread
    int lrow[4], lch[4];
#pragma unroll
    for (int i = 0; i < 4; i++) {
        int idx = tid + 256 * i;
        lrow[i] = idx >> 3;
        lch[i]  = idx & 7;
    }

    auto issue_loads = [&](int s, int buf) {
        int seg = s >> 4;
        int k0  = (s & 15) * 64;
        const __nv_bfloat16* aseg = (seg == 1) ? Al : Ah;
        const __nv_bfloat16* wseg = (seg == 2) ? WlZ : WhZ;
        uint32_t abase = sb + buf * 32768u;
        uint32_t bbase = abase + 16384u;
#pragma unroll
        for (int i = 0; i < 4; i++) {
            int row = lrow[i], ch = lch[i];
            uint32_t swz = (uint32_t)((ch ^ (row & 7)) << 4) + row * 128;
            cp_async16(abase + swz, aseg + (size_t)(m0 + row) * 1024 + k0 + ch * 8);
            cp_async16(bbase + swz, wseg + (size_t)(n0 + row) * 1024 + k0 + ch * 8);
        }
        cp_commit();
    };

    float c[2][8][4];
#pragma unroll
    for (int i = 0; i < 2; i++)
#pragma unroll
        for (int j = 0; j < 8; j++)
#pragma unroll
            for (int q = 0; q < 4; q++) c[i][j][q] = 0.f;

    // per-lane fragment rows (constant across k)
    const int mrowA0 = wm + ((lane >> 3) & 1) * 8 + (lane & 7);       // + 16*i
    const int kcA    = (lane >> 4) & 1;
    const int nrowB0 = wn + ((lane >> 4) & 1) * 8 + (lane & 7);       // + 16*j
    const int kcB    = (lane >> 3) & 1;

    issue_loads(0, 0);

    for (int s = 0; s < 48; s++) {
        const int buf = s & 1;
        cp_wait0();
        __syncthreads();
        if (s < 47) issue_loads(s + 1, buf ^ 1);

        const uint32_t abase = sb + buf * 32768u;
        const uint32_t bbase = abase + 16384u;
#pragma unroll
        for (int k16 = 0; k16 < 4; k16++) {
            uint32_t a[2][4];
#pragma unroll
            for (int i = 0; i < 2; i++) {
                int mr = mrowA0 + 16 * i;
                uint32_t addr = abase + mr * 128 +
                    ((((k16 << 1) | kcA) ^ (mr & 7)) << 4);
                ldmx4(a[i], addr);
            }
            uint32_t b[4][4];
#pragma unroll
            for (int j = 0; j < 4; j++) {
                int nr = nrowB0 + 16 * j;
                uint32_t addr = bbase + nr * 128 +
                    ((((k16 << 1) | kcB) ^ (nr & 7)) << 4);
                ldmx4(b[j], addr);
            }
#pragma unroll
            for (int i = 0; i < 2; i++)
#pragma unroll
                for (int j = 0; j < 4; j++) {
                    mma_bf16(c[i][2 * j],     a[i], b[j][0], b[j][1]);
                    mma_bf16(c[i][2 * j + 1], a[i], b[j][2], b[j][3]);
                }
        }
        __syncthreads();
    }

    // epilogue
    const int g = lane >> 2, tig = lane & 3;
#pragma unroll
    for (int i = 0; i < 2; i++) {
        int mrow = m0 + wm + 16 * i + g;
#pragma unroll
        for (int nt = 0; nt < 8; nt++) {
            int col = n0 + wn + nt * 8 + tig * 2;
            float* p = D + (size_t)mrow * 1024 + col;
            *reinterpret_cast<float2*>(p) = make_float2(c[i][nt][0], c[i][nt][1]);
            *reinterpret_cast<float2*>(p + 8 * 1024) = make_float2(c[i][nt][2], c[i][nt][3]);
        }
    }
}

// ---------------------------------------------------------------------------
// RoPE cos/sin table (double-precision trig of the fp32-rounded angle)
// ---------------------------------------------------------------------------
__global__ void rope_table_kernel()
{
    int idx = blockIdx.x * 256 + threadIdx.x;   // 65536
    int s = idx >> 5, i = idx & 31;
    double inv = exp(-((double)(2 * i) / 64.0) * log(10000.0));
    float  angf = (float)s * (float)inv;        // fp32 angle, like the reference
    double ang  = (double)angf;
    g_cos[idx] = (float)cos(ang);
    g_sin[idx] = (float)sin(ang);
}

// In-place interleaved RoPE on q|k region of g_qkv ([m][1024] layout).
__global__ void rope_qk_kernel(float* __restrict__ qk)
{
    int idx = blockIdx.x * 256 + threadIdx.x;
    int rp = idx & 511;          // pair within a 1024-float row
    int i  = rp & 31;            // pair within a 64-float head
    int m  = idx >> 9;
    int s  = m & 2047;
    float cv = g_cos[s * 32 + i];
    float sv = g_sin[s * 32 + i];
    float2* p = reinterpret_cast<float2*>(qk);
    float2 x = p[idx];
    p[idx] = make_float2(x.x * cv - x.y * sv, x.x * sv + x.y * cv);
}

// ---------------------------------------------------------------------------
// Causal flash attention, fp32, 64x64 tiles, DH=64. Q/K/V in [m][1024] layout
// (head h occupies columns h*64..h*64+63; row stride 1024 floats).
// ---------------------------------------------------------------------------
__global__ __launch_bounds__(256, 2)
void fattn_kernel(const float* __restrict__ Q, const float* __restrict__ K,
                  const float* __restrict__ V, float* __restrict__ att)
{
    __shared__ __align__(16) float Qt[64][64];    // [dh][r]
    __shared__ __align__(16) float KtPs[64][64];  // Kt: [dh][c] during S; Ps: [r][k] after
    __shared__ __align__(16) float Vs[64][64];    // [k][d]

    const int tid = threadIdx.x, tx = tid & 15, ty = tid >> 4;
    const int qi = gridDim.x - 1 - blockIdx.x;    // heavy tiles first
    const int bh = blockIdx.y;
    const int b = bh >> 4, h = bh & 15;

    const float* qb = Q + ((size_t)(b * S_ + qi * 64)) * 1024 + h * 64;
#pragma unroll
    for (int it = 0; it < 4; it++) {
        int idx = tid + it * 256;
        int r = idx >> 4, c4 = (idx & 15) << 2;
        float4 tq = *reinterpret_cast<const float4*>(qb + (size_t)r * 1024 + c4);
        Qt[c4 + 0][r] = tq.x; Qt[c4 + 1][r] = tq.y;
        Qt[c4 + 2][r] = tq.z; Qt[c4 + 3][r] = tq.w;
    }

    float2 o[4][2];
    float  mi[4], li[4];
#pragma unroll
    for (int i = 0; i < 4; i++) {
        o[i][0] = o[i][1] = make_float2(0.f, 0.f);
        mi[i] = -1e30f; li[i] = 0.f;
    }

    for (int j = 0; j <= qi; j++) {
        const float* kb = K + ((size_t)(b * S_ + j * 64)) * 1024 + h * 64;
        const float* vb = V + ((size_t)(b * S_ + j * 64)) * 1024 + h * 64;
        __syncthreads();
#pragma unroll
        for (int it = 0; it < 4; it++) {
            int idx = tid + it * 256;
            int r = idx >> 4, c4 = (idx & 15) << 2;
            float4 tk = *reinterpret_cast<const float4*>(kb + (size_t)r * 1024 + c4);
            KtPs[c4 + 0][r] = tk.x; KtPs[c4 + 1][r] = tk.y;
            KtPs[c4 + 2][r] = tk.z; KtPs[c4 + 3][r] = tk.w;
            float4 tv = *reinterpret_cast<const float4*>(vb + (size_t)r * 1024 + c4);
            *reinterpret_cast<float4*>(&Vs[r][c4]) = tv;
        }
        __syncthreads();

        // S = Q K^T
        float2 s2[4][2];
#pragma unroll
        for (int i = 0; i < 4; i++) s2[i][0] = s2[i][1] = make_float2(0.f, 0.f);
#pragma unroll 16
        for (int d = 0; d < 64; d++) {
            float4 aq = *reinterpret_cast<const float4*>(&Qt[d][ty * 4]);
            float4 bk = *reinterpret_cast<const float4*>(&KtPs[d][tx * 4]);
            float  aqv[4] = {aq.x, aq.y, aq.z, aq.w};
            float2 bkv[2] = {make_float2(bk.x, bk.y), make_float2(bk.z, bk.w)};
#pragma unroll
            for (int i = 0; i < 4; i++) {
                float2 aa = make_float2(aqv[i], aqv[i]);
                s2[i][0] = ffma2(aa, bkv[0], s2[i][0]);
                s2[i][1] = ffma2(aa, bkv[1], s2[i][1]);
            }
        }
        __syncthreads();   // Kt reads complete; smem becomes Ps

        float sv[4][4];
#pragma unroll
        for (int i = 0; i < 4; i++) {
            sv[i][0] = s2[i][0].x * 0.125f; sv[i][1] = s2[i][0].y * 0.125f;
            sv[i][2] = s2[i][1].x * 0.125f; sv[i][3] = s2[i][1].y * 0.125f;
        }
        if (j == qi) {
#pragma unroll
            for (int i = 0; i < 4; i++)
#pragma unroll
                for (int jj = 0; jj < 4; jj++)
                    if (tx * 4 + jj > ty * 4 + i) sv[i][jj] = -1e30f;
        }

#pragma unroll
        for (int i = 0; i < 4; i++) {
            float rm = fmaxf(fmaxf(sv[i][0], sv[i][1]), fmaxf(sv[i][2], sv[i][3]));
#pragma unroll
            for (int off = 1; off < 16; off <<= 1)
                rm = fmaxf(rm, __shfl_xor_sync(0xffffffffu, rm, off));
            float mn = fmaxf(mi[i], rm);
            float al = __expf(mi[i] - mn);
            mi[i] = mn;
            li[i] *= al;
            o[i][0].x *= al; o[i][0].y *= al; o[i][1].x *= al; o[i][1].y *= al;
            float p0 = __expf(sv[i][0] - mn), p1 = __expf(sv[i][1] - mn);
            float p2 = __expf(sv[i][2] - mn), p3 = __expf(sv[i][3] - mn);
            float rs = p0 + p1 + p2 + p3;
#pragma unroll
            for (int off = 1; off < 16; off <<= 1)
                rs += __shfl_xor_sync(0xffffffffu, rs, off);
            li[i] += rs;
            *reinterpret_cast<float4*>(&KtPs[ty * 4 + i][tx * 4]) = make_float4(p0, p1, p2, p3);
        }
        __syncthreads();

        // O += P @ V
#pragma unroll 16
        for (int kk = 0; kk < 64; kk++) {
            float4 vv = *reinterpret_cast<const float4*>(&Vs[kk][tx * 4]);
            float2 v2[2] = {make_float2(vv.x, vv.y), make_float2(vv.z, vv.w)};
#pragma unroll
            for (int i = 0; i < 4; i++) {
                float pr = KtPs[ty * 4 + i][kk];
                float2 aa = make_float2(pr, pr);
                o[i][0] = ffma2(aa, v2[0], o[i][0]);
                o[i][1] = ffma2(aa, v2[1], o[i][1]);
            }
        }
    }

#pragma unroll
    for (int i = 0; i < 4; i++) {
        float inv = 1.0f / li[i];
        int s = qi * 64 + ty * 4 + i;
        float* dst = att + ((size_t)(b * S_ + s)) * D_ + h * 64 + tx * 4;
        *reinterpret_cast<float4*>(dst) =
            make_float4(o[i][0].x * inv, o[i][0].y * inv, o[i][1].x * inv, o[i][1].y * inv);
    }
}

// ---------------------------------------------------------------------------
extern "C" void kernel_launch(void* const* d_in, const int* in_sizes, int n_in,
                              void* d_out, int out_size)
{
    (void)in_sizes; (void)n_in; (void)out_size;
    const float* x  = (const float*)d_in[0];
    const float* wq = (const float*)d_in[1];
    const float* wk = (const float*)d_in[2];
    const float* wv = (const float*)d_in[3];
    const float* wo = (const float*)d_in[4];
    float* out = (float*)d_out;

    float *pqkv, *patt;
    __nv_bfloat16 *pah, *pal, *pwh, *pwl;
    cudaGetSymbolAddress((void**)&pqkv, g_qkv);
    cudaGetSymbolAddress((void**)&patt, g_att);
    cudaGetSymbolAddress((void**)&pah,  g_ah);
    cudaGetSymbolAddress((void**)&pal,  g_al);
    cudaGetSymbolAddress((void**)&pwh,  g_wh);
    cudaGetSymbolAddress((void**)&pwl,  g_wl);
    float* pq = pqkv;
    float* pk = pqkv + QKV_STRIDE;
    float* pv = pqkv + 2 * QKV_STRIDE;

    cudaFuncSetAttribute(gemm_bf3, cudaFuncAttributeMaxDynamicSharedMemorySize, GEMM_SMEM);

    // splits
    const int n4x = M_TOT * D_ / 4;      // 2097152
    const int n4w = D_ * D_ / 4;         // 262144
    split_kernel<<<n4x / 256, 256>>>(x,  pah, pal, n4x);
    split_kernel<<<n4w / 256, 256>>>(wq, pwh + 0 * W_STRIDE, pwl + 0 * W_STRIDE, n4w);
    split_kernel<<<n4w / 256, 256>>>(wk, pwh + 1 * W_STRIDE, pwl + 1 * W_STRIDE, n4w);
    split_kernel<<<n4w / 256, 256>>>(wv, pwh + 2 * W_STRIDE, pwl + 2 * W_STRIDE, n4w);
    split_kernel<<<n4w / 256, 256>>>(wo, pwh + 3 * W_STRIDE, pwl + 3 * W_STRIDE, n4w);

    // fused QKV projection (z = 0,1,2)
    gemm_bf3<<<dim3(8, 64, 3), 256, GEMM_SMEM>>>(pah, pal, pwh, pwl, pqkv, QKV_STRIDE);

    rope_table_kernel<<<(S_ * 32) / 256, 256>>>();
    rope_qk_kernel<<<(2 * M_TOT * 512) / 256, 256>>>(pq);   // q and k in one pass

    fattn_kernel<<<dim3(S_ / 64, B_ * H_), 256>>>(pq, pk, pv, patt);

    // output projection: split att, then gemm with wo (index 3)
    split_kernel<<<n4x / 256, 256>>>(patt, pah, pal, n4x);
    gemm_bf3<<<dim3(8, 64, 1), 256, GEMM_SMEM>>>(pah, pal,
        pwh + 3 * W_STRIDE, pwl + 3 * W_STRIDE, out, 0);
}

// round 4
// speedup vs baseline: 3.0782x; 1.7122x over previous
#include <cuda_runtime.h>
#include <cuda_bf16.h>
#include <cstdint>

// ---------------------------------------------------------------------------
// Problem constants
// ---------------------------------------------------------------------------
constexpr int B_  = 4;
constexpr int S_  = 2048;
constexpr int D_  = 1024;
constexpr int H_  = 16;
constexpr int DH_ = 64;
constexpr int M_TOT = B_ * S_;                    // 8192
constexpr size_t QKV_STRIDE = (size_t)M_TOT * D_; // 8388608 floats
constexpr size_t W_STRIDE   = (size_t)D_ * D_;    // 1048576

// Scratch (device globals: allocation-free rule)
__device__ float g_qkv[3 * M_TOT * D_];           // q | k | v, each [8192][1024]
__device__ float g_att[M_TOT * D_];
__device__ float g_cos[S_ * (DH_ / 2)];
__device__ float g_sin[S_ * (DH_ / 2)];
__device__ __nv_bfloat16 g_ah[M_TOT * D_];        // hi split of activation
__device__ __nv_bfloat16 g_al[M_TOT * D_];        // lo split
__device__ __nv_bfloat16 g_wh[4 * W_STRIDE];      // hi split of wq|wk|wv|wo
__device__ __nv_bfloat16 g_wl[4 * W_STRIDE];      // lo split
__device__ __nv_bfloat16 g_qkh[2 * M_TOT * D_];   // hi split of roped q|k
__device__ __nv_bfloat16 g_qkl[2 * M_TOT * D_];   // lo split
__device__ __nv_bfloat16 g_vth[M_TOT * D_];       // V^T hi: [bh][d][s]
__device__ __nv_bfloat16 g_vtl[M_TOT * D_];       // V^T lo

// ---------------------------------------------------------------------------
// helpers
// ---------------------------------------------------------------------------
__device__ __forceinline__ uint32_t smem_to_u32(const void* smem_ptr) {
    uint32_t addr;
    asm("{ .reg .u64 tmp; cvta.to.shared.u64 tmp, %1; cvt.u32.u64 %0, tmp; }"
        : "=r"(addr) : "l"(smem_ptr));
    return addr;
}

__device__ __forceinline__ void cp_async16(uint32_t saddr, const void* gptr) {
    asm volatile("cp.async.cg.shared.global [%0], [%1], 16;"
                 :: "r"(saddr), "l"(gptr) : "memory");
}
__device__ __forceinline__ void cp_commit() {
    asm volatile("cp.async.commit_group;" ::: "memory");
}
__device__ __forceinline__ void cp_wait0() {
    asm volatile("cp.async.wait_group 0;" ::: "memory");
}

__device__ __forceinline__ void ldmx4(uint32_t* r, uint32_t addr) {
    asm volatile("ldmatrix.sync.aligned.m8n8.x4.shared.b16 {%0,%1,%2,%3}, [%4];"
                 : "=r"(r[0]), "=r"(r[1]), "=r"(r[2]), "=r"(r[3]) : "r"(addr));
}

__device__ __forceinline__ void mma_bf16(float* c, const uint32_t* a,
                                         uint32_t b0, uint32_t b1) {
    asm volatile(
        "mma.sync.aligned.m16n8k16.row.col.f32.bf16.bf16.f32 "
        "{%0,%1,%2,%3}, {%4,%5,%6,%7}, {%8,%9}, {%0,%1,%2,%3};"
        : "+f"(c[0]), "+f"(c[1]), "+f"(c[2]), "+f"(c[3])
        : "r"(a[0]), "r"(a[1]), "r"(a[2]), "r"(a[3]), "r"(b0), "r"(b1));
}

__device__ __forceinline__ uint32_t pack2bf(__nv_bfloat16 a, __nv_bfloat16 b) {
    return (uint32_t)__bfloat16_as_ushort(a) | ((uint32_t)__bfloat16_as_ushort(b) << 16);
}

// pack hi/lo bf16 splits of two floats
__device__ __forceinline__ void split2pack(float x, float y, uint32_t& h, uint32_t& l) {
    __nv_bfloat16 hx = __float2bfloat16(x), hy = __float2bfloat16(y);
    __nv_bfloat16 lx = __float2bfloat16(x - __bfloat162float(hx));
    __nv_bfloat16 ly = __float2bfloat16(y - __bfloat162float(hy));
    h = pack2bf(hx, hy);
    l = pack2bf(lx, ly);
}

// ---------------------------------------------------------------------------
// Split fp32 -> (hi, lo) bf16
// ---------------------------------------------------------------------------
__global__ void split_kernel(const float* __restrict__ src,
                             __nv_bfloat16* __restrict__ hi,
                             __nv_bfloat16* __restrict__ lo, int n4)
{
    int i = blockIdx.x * 256 + threadIdx.x;
    if (i >= n4) return;
    float4 v = reinterpret_cast<const float4*>(src)[i];
    uint32_t h0, l0, h1, l1;
    split2pack(v.x, v.y, h0, l0);
    split2pack(v.z, v.w, h1, l1);
    reinterpret_cast<uint2*>(hi)[i] = make_uint2(h0, h1);
    reinterpret_cast<uint2*>(lo)[i] = make_uint2(l0, l1);
}

// ---------------------------------------------------------------------------
// V transpose + split: v[b*2048+s][h*64+d] -> vt[bh][d][s] (hi/lo bf16)
// grid (64 s-tiles, 2 d-tiles, 64 bh), block 256 (32x8)
// ---------------------------------------------------------------------------
__global__ void vtrans_kernel(const float* __restrict__ v,
                              __nv_bfloat16* __restrict__ vth,
                              __nv_bfloat16* __restrict__ vtl)
{
    __shared__ float t[32][33];
    const int st = blockIdx.x, dt = blockIdx.y, bh = blockIdx.z;
    const int b = bh >> 4, h = bh & 15;
    const int lx = threadIdx.x & 31, ly = threadIdx.x >> 5;
#pragma unroll
    for (int i = 0; i < 4; i++) {
        int s = st * 32 + ly + 8 * i;
        t[ly + 8 * i][lx] = v[(size_t)(b * 2048 + s) * 1024 + h * 64 + dt * 32 + lx];
    }
    __syncthreads();
#pragma unroll
    for (int i = 0; i < 4; i++) {
        int d = dt * 32 + ly + 8 * i;
        float val = t[lx][ly + 8 * i];
        __nv_bfloat16 hi = __float2bfloat16(val);
        __nv_bfloat16 lo = __float2bfloat16(val - __bfloat162float(hi));
        size_t idx = ((size_t)bh * 64 + d) * 2048 + st * 32 + lx;
        vth[idx] = hi;
        vtl[idx] = lo;
    }
}

// ---------------------------------------------------------------------------
// bf16 mma.sync GEMM with 3-term fp32 emulation (unchanged from R3).
// ---------------------------------------------------------------------------
constexpr int GEMM_SMEM = 65536;

__global__ void __launch_bounds__(256)
gemm_bf3(const __nv_bfloat16* __restrict__ Ah, const __nv_bfloat16* __restrict__ Al,
         const __nv_bfloat16* __restrict__ Wh, const __nv_bfloat16* __restrict__ Wl,
         float* __restrict__ Dst, size_t dstride)
{
    extern __shared__ char smem[];
    const uint32_t sb = smem_to_u32(smem);
    const int tid = threadIdx.x, lane = tid & 31, wid = tid >> 5;
    const int z = blockIdx.z;
    const __nv_bfloat16* WhZ = Wh + (size_t)z * W_STRIDE;
    const __nv_bfloat16* WlZ = Wl + (size_t)z * W_STRIDE;
    float* D = Dst + (size_t)z * dstride;
    const int m0 = blockIdx.y * 128, n0 = blockIdx.x * 128;
    const int wm = (wid >> 1) * 32, wn = (wid & 1) * 64;

    int lrow[4], lch[4];
#pragma unroll
    for (int i = 0; i < 4; i++) {
        int idx = tid + 256 * i;
        lrow[i] = idx >> 3;
        lch[i]  = idx & 7;
    }

    auto issue_loads = [&](int s, int buf) {
        int seg = s >> 4;
        int k0  = (s & 15) * 64;
        const __nv_bfloat16* aseg = (seg == 1) ? Al : Ah;
        const __nv_bfloat16* wseg = (seg == 2) ? WlZ : WhZ;
        uint32_t abase = sb + buf * 32768u;
        uint32_t bbase = abase + 16384u;
#pragma unroll
        for (int i = 0; i < 4; i++) {
            int row = lrow[i], ch = lch[i];
            uint32_t swz = (uint32_t)((ch ^ (row & 7)) << 4) + row * 128;
            cp_async16(abase + swz, aseg + (size_t)(m0 + row) * 1024 + k0 + ch * 8);
            cp_async16(bbase + swz, wseg + (size_t)(n0 + row) * 1024 + k0 + ch * 8);
        }
        cp_commit();
    };

    float c[2][8][4];
#pragma unroll
    for (int i = 0; i < 2; i++)
#pragma unroll
        for (int j = 0; j < 8; j++)
#pragma unroll
            for (int q = 0; q < 4; q++) c[i][j][q] = 0.f;

    const int mrowA0 = wm + ((lane >> 3) & 1) * 8 + (lane & 7);
    const int kcA    = (lane >> 4) & 1;
    const int nrowB0 = wn + ((lane >> 4) & 1) * 8 + (lane & 7);
    const int kcB    = (lane >> 3) & 1;

    issue_loads(0, 0);

    for (int s = 0; s < 48; s++) {
        const int buf = s & 1;
        cp_wait0();
        __syncthreads();
        if (s < 47) issue_loads(s + 1, buf ^ 1);

        const uint32_t abase = sb + buf * 32768u;
        const uint32_t bbase = abase + 16384u;
#pragma unroll
        for (int k16 = 0; k16 < 4; k16++) {
            uint32_t a[2][4];
#pragma unroll
            for (int i = 0; i < 2; i++) {
                int mr = mrowA0 + 16 * i;
                uint32_t addr = abase + mr * 128 +
                    ((((k16 << 1) | kcA) ^ (mr & 7)) << 4);
                ldmx4(a[i], addr);
            }
            uint32_t b[4][4];
#pragma unroll
            for (int j = 0; j < 4; j++) {
                int nr = nrowB0 + 16 * j;
                uint32_t addr = bbase + nr * 128 +
                    ((((k16 << 1) | kcB) ^ (nr & 7)) << 4);
                ldmx4(b[j], addr);
            }
#pragma unroll
            for (int i = 0; i < 2; i++)
#pragma unroll
                for (int j = 0; j < 4; j++) {
                    mma_bf16(c[i][2 * j],     a[i], b[j][0], b[j][1]);
                    mma_bf16(c[i][2 * j + 1], a[i], b[j][2], b[j][3]);
                }
        }
        __syncthreads();
    }

    const int g = lane >> 2, tig = lane & 3;
#pragma unroll
    for (int i = 0; i < 2; i++) {
        int mrow = m0 + wm + 16 * i + g;
#pragma unroll
        for (int nt = 0; nt < 8; nt++) {
            int col = n0 + wn + nt * 8 + tig * 2;
            float* p = D + (size_t)mrow * 1024 + col;
            *reinterpret_cast<float2*>(p) = make_float2(c[i][nt][0], c[i][nt][1]);
            *reinterpret_cast<float2*>(p + 8 * 1024) = make_float2(c[i][nt][2], c[i][nt][3]);
        }
    }
}

// ---------------------------------------------------------------------------
// RoPE
// ---------------------------------------------------------------------------
__global__ void rope_table_kernel()
{
    int idx = blockIdx.x * 256 + threadIdx.x;   // 65536
    int s = idx >> 5, i = idx & 31;
    double inv = exp(-((double)(2 * i) / 64.0) * log(10000.0));
    float  angf = (float)s * (float)inv;
    double ang  = (double)angf;
    g_cos[idx] = (float)cos(ang);
    g_sin[idx] = (float)sin(ang);
}

__global__ void rope_qk_kernel(float* __restrict__ qk)
{
    int idx = blockIdx.x * 256 + threadIdx.x;
    int rp = idx & 511;
    int i  = rp & 31;
    int m  = idx >> 9;
    int s  = m & 2047;
    float cv = g_cos[s * 32 + i];
    float sv = g_sin[s * 32 + i];
    float2* p = reinterpret_cast<float2*>(qk);
    float2 x = p[idx];
    p[idx] = make_float2(x.x * cv - x.y * sv, x.x * sv + x.y * cv);
}

// ---------------------------------------------------------------------------
// Tensor-core causal flash attention (mma.sync bf16, 3-term emulation).
// BQ=128, BK=64, DH=64. 256 threads = 8 warps x 16 q-rows.
// Q/K from pre-split g_qkh/g_qkl ([m][1024], head cols). V from g_vth/g_vtl
// ([bh][d][s]). Output fp32 to g_att [m][1024].
// smem: Qh(16K) Ql(16K) Kh(8K) Kl(8K) Vth(8K) Vtl(8K) = 64KB
// ---------------------------------------------------------------------------
constexpr int ATT_SMEM = 65536;
constexpr uint32_t QH_O = 0, QL_O = 16384, KH_O = 32768, KL_O = 40960,
                   VTH_O = 49152, VTL_O = 57344;

__global__ void __launch_bounds__(256, 1)
fattn_tc(const __nv_bfloat16* __restrict__ QKh,
         const __nv_bfloat16* __restrict__ QKl,
         const __nv_bfloat16* __restrict__ Vth,
         const __nv_bfloat16* __restrict__ Vtl,
         float* __restrict__ att)
{
    extern __shared__ char smem[];
    const uint32_t sb = smem_to_u32(smem);
    const int tid = threadIdx.x, lane = tid & 31, w = tid >> 5;
    const int qt = (int)gridDim.x - 1 - (int)blockIdx.x;   // heavy tiles first
    const int bh = blockIdx.y;
    const int b = bh >> 4, h = bh & 15;
    const int q0 = qt * 128;

    // load Q tile (hi/lo)
#pragma unroll
    for (int i = 0; i < 4; i++) {
        int idx = tid + 256 * i;
        int r = idx >> 3, ch = idx & 7;
        size_t gq = (size_t)(b * 2048 + q0 + r) * 1024 + h * 64 + ch * 8;
        uint32_t sw = r * 128 + ((ch ^ (r & 7)) << 4);
        cp_async16(sb + QH_O + sw, QKh + gq);
        cp_async16(sb + QL_O + sw, QKl + gq);
    }
    cp_commit();

    float o[8][4];
#pragma unroll
    for (int nt = 0; nt < 8; nt++)
#pragma unroll
        for (int q = 0; q < 4; q++) o[nt][q] = 0.f;
    float m0 = -1e30f, m1 = -1e30f, l0 = 0.f, l1 = 0.f;

    const int g_  = lane >> 2, tig = lane & 3;
    const int mrA = w * 16 + ((lane >> 3) & 1) * 8 + (lane & 7);
    const int kcA = (lane >> 4) & 1;
    const int nrB = ((lane >> 4) & 1) * 8 + (lane & 7);
    const int kcB = (lane >> 3) & 1;
    const int row0 = q0 + w * 16 + g_;      // lane's first q-row

    cp_wait0();
    __syncthreads();

    const int njk = 2 * qt + 2;
    for (int jk = 0; jk < njk; jk++) {
        // load K tile (hi/lo) and Vt tile (hi/lo)
#pragma unroll
        for (int i = 0; i < 2; i++) {
            int idx = tid + 256 * i;
            int r = idx >> 3, ch = idx & 7;
            uint32_t sw = r * 128 + ((ch ^ (r & 7)) << 4);
            size_t gk = QKV_STRIDE + (size_t)(b * 2048 + jk * 64 + r) * 1024 + h * 64 + ch * 8;
            cp_async16(sb + KH_O + sw, QKh + gk);
            cp_async16(sb + KL_O + sw, QKl + gk);
            size_t gv = ((size_t)bh * 64 + r) * 2048 + jk * 64 + ch * 8;
            cp_async16(sb + VTH_O + sw, Vth + gv);
            cp_async16(sb + VTL_O + sw, Vtl + gv);
        }
        cp_commit();
        cp_wait0();
        __syncthreads();

        // ---- S = Q K^T (3-term) ----
        float c[8][4];
#pragma unroll
        for (int nt = 0; nt < 8; nt++)
#pragma unroll
            for (int q = 0; q < 4; q++) c[nt][q] = 0.f;

#pragma unroll
        for (int k16 = 0; k16 < 4; k16++) {
            uint32_t ah[4], al[4];
            uint32_t aaddr = sb + QH_O + mrA * 128 +
                ((((k16 << 1) | kcA) ^ (mrA & 7)) << 4);
            ldmx4(ah, aaddr);
            ldmx4(al, aaddr + (QL_O - QH_O));
#pragma unroll
            for (int j = 0; j < 4; j++) {
                int nr = 16 * j + nrB;
                uint32_t baddr = sb + KH_O + nr * 128 +
                    ((((k16 << 1) | kcB) ^ (nr & 7)) << 4);
                uint32_t bhh[4], bll[4];
                ldmx4(bhh, baddr);
                ldmx4(bll, baddr + 8192);
                mma_bf16(c[2 * j],     ah, bhh[0], bhh[1]);
                mma_bf16(c[2 * j + 1], ah, bhh[2], bhh[3]);
                mma_bf16(c[2 * j],     al, bhh[0], bhh[1]);
                mma_bf16(c[2 * j + 1], al, bhh[2], bhh[3]);
                mma_bf16(c[2 * j],     ah, bll[0], bll[1]);
                mma_bf16(c[2 * j + 1], ah, bll[2], bll[3]);
            }
        }

        // ---- scale + causal mask ----
#pragma unroll
        for (int nt = 0; nt < 8; nt++)
#pragma unroll
            for (int q = 0; q < 4; q++) c[nt][q] *= 0.125f;

        if (jk >= 2 * qt) {   // only the two diagonal-adjacent tiles need masking
#pragma unroll
            for (int nt = 0; nt < 8; nt++) {
                int colg = jk * 64 + 8 * nt + 2 * tig;
                if (colg     > row0)     c[nt][0] = -1e30f;
                if (colg + 1 > row0)     c[nt][1] = -1e30f;
                if (colg     > row0 + 8) c[nt][2] = -1e30f;
                if (colg + 1 > row0 + 8) c[nt][3] = -1e30f;
            }
        }

        // ---- online softmax ----
        float rm0 = -1e30f, rm1 = -1e30f;
#pragma unroll
        for (int nt = 0; nt < 8; nt++) {
            rm0 = fmaxf(rm0, fmaxf(c[nt][0], c[nt][1]));
            rm1 = fmaxf(rm1, fmaxf(c[nt][2], c[nt][3]));
        }
        rm0 = fmaxf(rm0, __shfl_xor_sync(0xffffffffu, rm0, 1));
        rm0 = fmaxf(rm0, __shfl_xor_sync(0xffffffffu, rm0, 2));
        rm1 = fmaxf(rm1, __shfl_xor_sync(0xffffffffu, rm1, 1));
        rm1 = fmaxf(rm1, __shfl_xor_sync(0xffffffffu, rm1, 2));

        float mn0 = fmaxf(m0, rm0), mn1 = fmaxf(m1, rm1);
        float a0 = __expf(m0 - mn0), a1 = __expf(m1 - mn1);
        m0 = mn0; m1 = mn1;

        float rs0 = 0.f, rs1 = 0.f;
#pragma unroll
        for (int nt = 0; nt < 8; nt++) {
            c[nt][0] = __expf(c[nt][0] - mn0);
            c[nt][1] = __expf(c[nt][1] - mn0);
            c[nt][2] = __expf(c[nt][2] - mn1);
            c[nt][3] = __expf(c[nt][3] - mn1);
            rs0 += c[nt][0] + c[nt][1];
            rs1 += c[nt][2] + c[nt][3];
        }
        rs0 += __shfl_xor_sync(0xffffffffu, rs0, 1);
        rs0 += __shfl_xor_sync(0xffffffffu, rs0, 2);
        rs1 += __shfl_xor_sync(0xffffffffu, rs1, 1);
        rs1 += __shfl_xor_sync(0xffffffffu, rs1, 2);
        l0 = l0 * a0 + rs0;
        l1 = l1 * a1 + rs1;
#pragma unroll
        for (int nt = 0; nt < 8; nt++) {
            o[nt][0] *= a0; o[nt][1] *= a0;
            o[nt][2] *= a1; o[nt][3] *= a1;
        }

        // ---- O += P V (3-term); P a-frags built from c-frags ----
#pragma unroll
        for (int k16 = 0; k16 < 4; k16++) {
            uint32_t aph[4], apl[4];
            split2pack(c[2 * k16][0],     c[2 * k16][1],     aph[0], apl[0]);
            split2pack(c[2 * k16][2],     c[2 * k16][3],     aph[1], apl[1]);
            split2pack(c[2 * k16 + 1][0], c[2 * k16 + 1][1], aph[2], apl[2]);
            split2pack(c[2 * k16 + 1][2], c[2 * k16 + 1][3], aph[3], apl[3]);
#pragma unroll
            for (int j = 0; j < 4; j++) {
                int nr = 16 * j + nrB;
                uint32_t baddr = sb + VTH_O + nr * 128 +
                    ((((k16 << 1) | kcB) ^ (nr & 7)) << 4);
                uint32_t vhh[4], vll[4];
                ldmx4(vhh, baddr);
                ldmx4(vll, baddr + 8192);
                mma_bf16(o[2 * j],     aph, vhh[0], vhh[1]);
                mma_bf16(o[2 * j + 1], aph, vhh[2], vhh[3]);
                mma_bf16(o[2 * j],     apl, vhh[0], vhh[1]);
                mma_bf16(o[2 * j + 1], apl, vhh[2], vhh[3]);
                mma_bf16(o[2 * j],     aph, vll[0], vll[1]);
                mma_bf16(o[2 * j + 1], aph, vll[2], vll[3]);
            }
        }
        __syncthreads();   // Vt/K reads done before next-iter overwrite
    }

    // ---- epilogue ----
    float inv0 = 1.0f / l0, inv1 = 1.0f / l1;
    float* base0 = att + (size_t)(b * 2048 + row0) * 1024 + h * 64 + 2 * tig;
    float* base1 = base0 + (size_t)8 * 1024;
#pragma unroll
    for (int nt = 0; nt < 8; nt++) {
        *reinterpret_cast<float2*>(base0 + 8 * nt) =
            make_float2(o[nt][0] * inv0, o[nt][1] * inv0);
        *reinterpret_cast<float2*>(base1 + 8 * nt) =
            make_float2(o[nt][2] * inv1, o[nt][3] * inv1);
    }
}

// ---------------------------------------------------------------------------
extern "C" void kernel_launch(void* const* d_in, const int* in_sizes, int n_in,
                              void* d_out, int out_size)
{
    (void)in_sizes; (void)n_in; (void)out_size;
    const float* x  = (const float*)d_in[0];
    const float* wq = (const float*)d_in[1];
    const float* wk = (const float*)d_in[2];
    const float* wv = (const float*)d_in[3];
    const float* wo = (const float*)d_in[4];
    float* out = (float*)d_out;

    float *pqkv, *patt;
    __nv_bfloat16 *pah, *pal, *pwh, *pwl, *pqkh, *pqkl, *pvth, *pvtl;
    cudaGetSymbolAddress((void**)&pqkv, g_qkv);
    cudaGetSymbolAddress((void**)&patt, g_att);
    cudaGetSymbolAddress((void**)&pah,  g_ah);
    cudaGetSymbolAddress((void**)&pal,  g_al);
    cudaGetSymbolAddress((void**)&pwh,  g_wh);
    cudaGetSymbolAddress((void**)&pwl,  g_wl);
    cudaGetSymbolAddress((void**)&pqkh, g_qkh);
    cudaGetSymbolAddress((void**)&pqkl, g_qkl);
    cudaGetSymbolAddress((void**)&pvth, g_vth);
    cudaGetSymbolAddress((void**)&pvtl, g_vtl);

    cudaFuncSetAttribute(gemm_bf3, cudaFuncAttributeMaxDynamicSharedMemorySize, GEMM_SMEM);
    cudaFuncSetAttribute(fattn_tc, cudaFuncAttributeMaxDynamicSharedMemorySize, ATT_SMEM);

    const int n4x = M_TOT * D_ / 4;      // 2097152
    const int n4w = D_ * D_ / 4;         // 262144
    split_kernel<<<n4x / 256, 256>>>(x,  pah, pal, n4x);
    split_kernel<<<n4w / 256, 256>>>(wq, pwh + 0 * W_STRIDE, pwl + 0 * W_STRIDE, n4w);
    split_kernel<<<n4w / 256, 256>>>(wk, pwh + 1 * W_STRIDE, pwl + 1 * W_STRIDE, n4w);
    split_kernel<<<n4w / 256, 256>>>(wv, pwh + 2 * W_STRIDE, pwl + 2 * W_STRIDE, n4w);
    split_kernel<<<n4w / 256, 256>>>(wo, pwh + 3 * W_STRIDE, pwl + 3 * W_STRIDE, n4w);

    // fused QKV projection (z = 0,1,2)
    gemm_bf3<<<dim3(8, 64, 3), 256, GEMM_SMEM>>>(pah, pal, pwh, pwl, pqkv, QKV_STRIDE);

    rope_table_kernel<<<(S_ * 32) / 256, 256>>>();
    rope_qk_kernel<<<(2 * M_TOT * 512) / 256, 256>>>(pqkv);   // q and k

    // attention input prep: split roped q|k; transpose+split v
    split_kernel<<<(2 * n4x) / 256, 256>>>(pqkv, pqkh, pqkl, 2 * n4x);
    vtrans_kernel<<<dim3(64, 2, 64), 256>>>(pqkv + 2 * QKV_STRIDE, pvth, pvtl);

    fattn_tc<<<dim3(16, 64), 256, ATT_SMEM>>>(pqkh, pqkl, pvth, pvtl, patt);

    // output projection
    split_kernel<<<n4x / 256, 256>>>(patt, pah, pal, n4x);
    gemm_bf3<<<dim3(8, 64, 1), 256, GEMM_SMEM>>>(pah, pal,
        pwh + 3 * W_STRIDE, pwl + 3 * W_STRIDE, out, 0);
}

// round 5
// speedup vs baseline: 3.4067x; 1.1067x over previous
#include <cuda_runtime.h>
#include <cuda_bf16.h>
#include <cstdint>

// ---------------------------------------------------------------------------
// Problem constants
// ---------------------------------------------------------------------------
constexpr int B_  = 4;
constexpr int S_  = 2048;
constexpr int D_  = 1024;
constexpr int H_  = 16;
constexpr int DH_ = 64;
constexpr int M_TOT = B_ * S_;                    // 8192
constexpr size_t QKV_STRIDE = (size_t)M_TOT * D_; // 8388608
constexpr size_t W_STRIDE   = (size_t)D_ * D_;    // 1048576

// Scratch (device globals: allocation-free rule)
__device__ float g_v[M_TOT * D_];                 // fp32 V (pre-transpose)
__device__ float g_cos[S_ * (DH_ / 2)];
__device__ float g_sin[S_ * (DH_ / 2)];
__device__ __nv_bfloat16 g_ah[M_TOT * D_];        // hi split: x, later attention out
__device__ __nv_bfloat16 g_al[M_TOT * D_];        // lo split
__device__ __nv_bfloat16 g_wh[4 * W_STRIDE];      // hi split of wq|wk|wv|wo
__device__ __nv_bfloat16 g_wl[4 * W_STRIDE];      // lo split
__device__ __nv_bfloat16 g_qkh[2 * M_TOT * D_];   // hi split of roped q|k
__device__ __nv_bfloat16 g_qkl[2 * M_TOT * D_];   // lo split
__device__ __nv_bfloat16 g_vth[M_TOT * D_];       // V^T hi: [bh][d][s]
__device__ __nv_bfloat16 g_vtl[M_TOT * D_];       // V^T lo

// ---------------------------------------------------------------------------
// helpers
// ---------------------------------------------------------------------------
__device__ __forceinline__ uint32_t smem_to_u32(const void* smem_ptr) {
    uint32_t addr;
    asm("{ .reg .u64 tmp; cvta.to.shared.u64 tmp, %1; cvt.u32.u64 %0, tmp; }"
        : "=r"(addr) : "l"(smem_ptr));
    return addr;
}

__device__ __forceinline__ void cp_async16(uint32_t saddr, const void* gptr) {
    asm volatile("cp.async.cg.shared.global [%0], [%1], 16;"
                 :: "r"(saddr), "l"(gptr) : "memory");
}
__device__ __forceinline__ void cp_commit() {
    asm volatile("cp.async.commit_group;" ::: "memory");
}
template <int N>
__device__ __forceinline__ void cp_wait() {
    asm volatile("cp.async.wait_group %0;" :: "n"(N) : "memory");
}

__device__ __forceinline__ void ldmx4(uint32_t* r, uint32_t addr) {
    asm volatile("ldmatrix.sync.aligned.m8n8.x4.shared.b16 {%0,%1,%2,%3}, [%4];"
                 : "=r"(r[0]), "=r"(r[1]), "=r"(r[2]), "=r"(r[3]) : "r"(addr));
}

__device__ __forceinline__ void mma_bf16(float* c, const uint32_t* a,
                                         uint32_t b0, uint32_t b1) {
    asm volatile(
        "mma.sync.aligned.m16n8k16.row.col.f32.bf16.bf16.f32 "
        "{%0,%1,%2,%3}, {%4,%5,%6,%7}, {%8,%9}, {%0,%1,%2,%3};"
        : "+f"(c[0]), "+f"(c[1]), "+f"(c[2]), "+f"(c[3])
        : "r"(a[0]), "r"(a[1]), "r"(a[2]), "r"(a[3]), "r"(b0), "r"(b1));
}

__device__ __forceinline__ uint32_t pack2bf(__nv_bfloat16 a, __nv_bfloat16 b) {
    return (uint32_t)__bfloat16_as_ushort(a) | ((uint32_t)__bfloat16_as_ushort(b) << 16);
}

__device__ __forceinline__ void split2pack(float x, float y, uint32_t& h, uint32_t& l) {
    __nv_bfloat16 hx = __float2bfloat16(x), hy = __float2bfloat16(y);
    __nv_bfloat16 lx = __float2bfloat16(x - __bfloat162float(hx));
    __nv_bfloat16 ly = __float2bfloat16(y - __bfloat162float(hy));
    h = pack2bf(hx, hy);
    l = pack2bf(lx, ly);
}

// ---------------------------------------------------------------------------
// Split fp32 -> (hi, lo) bf16
// ---------------------------------------------------------------------------
__global__ void split_kernel(const float* __restrict__ src,
                             __nv_bfloat16* __restrict__ hi,
                             __nv_bfloat16* __restrict__ lo, int n4)
{
    int i = blockIdx.x * 256 + threadIdx.x;
    if (i >= n4) return;
    float4 v = reinterpret_cast<const float4*>(src)[i];
    uint32_t h0, l0, h1, l1;
    split2pack(v.x, v.y, h0, l0);
    split2pack(v.z, v.w, h1, l1);
    reinterpret_cast<uint2*>(hi)[i] = make_uint2(h0, h1);
    reinterpret_cast<uint2*>(lo)[i] = make_uint2(l0, l1);
}

// ---------------------------------------------------------------------------
// V transpose + split: v[b*2048+s][h*64+d] -> vt[bh][d][s] (hi/lo bf16)
// ---------------------------------------------------------------------------
__global__ void vtrans_kernel(const float* __restrict__ v,
                              __nv_bfloat16* __restrict__ vth,
                              __nv_bfloat16* __restrict__ vtl)
{
    __shared__ float t[32][33];
    const int st = blockIdx.x, dt = blockIdx.y, bh = blockIdx.z;
    const int b = bh >> 4, h = bh & 15;
    const int lx = threadIdx.x & 31, ly = threadIdx.x >> 5;
#pragma unroll
    for (int i = 0; i < 4; i++) {
        int s = st * 32 + ly + 8 * i;
        t[ly + 8 * i][lx] = v[(size_t)(b * 2048 + s) * 1024 + h * 64 + dt * 32 + lx];
    }
    __syncthreads();
#pragma unroll
    for (int i = 0; i < 4; i++) {
        int d = dt * 32 + ly + 8 * i;
        float val = t[lx][ly + 8 * i];
        __nv_bfloat16 hi = __float2bfloat16(val);
        __nv_bfloat16 lo = __float2bfloat16(val - __bfloat162float(hi));
        size_t idx = ((size_t)bh * 64 + d) * 2048 + st * 32 + lx;
        vth[idx] = hi;
        vtl[idx] = lo;
    }
}

// ---------------------------------------------------------------------------
// RoPE cos/sin table
// ---------------------------------------------------------------------------
__global__ void rope_table_kernel()
{
    int idx = blockIdx.x * 256 + threadIdx.x;   // 65536
    int s = idx >> 5, i = idx & 31;
    double inv = exp(-((double)(2 * i) / 64.0) * log(10000.0));
    float  angf = (float)s * (float)inv;
    double ang  = (double)angf;
    g_cos[idx] = (float)cos(ang);
    g_sin[idx] = (float)sin(ang);
}

// ---------------------------------------------------------------------------
// bf16 mma.sync GEMM, 3-term fp32 emulation, 3-stage cp.async pipeline.
// fused=1 (QKV): z=0,1 -> RoPE in epilogue, write bf16 hi/lo to Dh/Dl+z*QS;
//                z=2   -> fp32 to Df (V).
// fused=0: fp32 to Df (final projection, gridDim.z==1).
// ---------------------------------------------------------------------------
constexpr int GEMM_SMEM = 98304;   // 3 stages * (16KB A + 16KB B)

__global__ void __launch_bounds__(256)
gemm_bf3(const __nv_bfloat16* __restrict__ Ah, const __nv_bfloat16* __restrict__ Al,
         const __nv_bfloat16* __restrict__ Wh, const __nv_bfloat16* __restrict__ Wl,
         float* __restrict__ Df, __nv_bfloat16* __restrict__ Dh,
         __nv_bfloat16* __restrict__ Dl, int fused)
{
    extern __shared__ char smem[];
    const uint32_t sb = smem_to_u32(smem);
    const int tid = threadIdx.x, lane = tid & 31, wid = tid >> 5;
    const int z = blockIdx.z;
    const __nv_bfloat16* WhZ = Wh + (size_t)z * W_STRIDE;
    const __nv_bfloat16* WlZ = Wl + (size_t)z * W_STRIDE;
    const int m0 = blockIdx.y * 128, n0 = blockIdx.x * 128;
    const int wm = (wid >> 1) * 32, wn = (wid & 1) * 64;

    int lrow[4], lch[4];
#pragma unroll
    for (int i = 0; i < 4; i++) {
        int idx = tid + 256 * i;
        lrow[i] = idx >> 3;
        lch[i]  = idx & 7;
    }

    auto issue_loads = [&](int s, int buf) {
        int seg = s >> 4;
        int k0  = (s & 15) * 64;
        const __nv_bfloat16* aseg = (seg == 1) ? Al : Ah;
        const __nv_bfloat16* wseg = (seg == 2) ? WlZ : WhZ;
        uint32_t abase = sb + buf * 32768u;
        uint32_t bbase = abase + 16384u;
#pragma unroll
        for (int i = 0; i < 4; i++) {
            int row = lrow[i], ch = lch[i];
            uint32_t swz = (uint32_t)((ch ^ (row & 7)) << 4) + row * 128;
            cp_async16(abase + swz, aseg + (size_t)(m0 + row) * 1024 + k0 + ch * 8);
            cp_async16(bbase + swz, wseg + (size_t)(n0 + row) * 1024 + k0 + ch * 8);
        }
        cp_commit();
    };

    float c[2][8][4];
#pragma unroll
    for (int i = 0; i < 2; i++)
#pragma unroll
        for (int j = 0; j < 8; j++)
#pragma unroll
            for (int q = 0; q < 4; q++) c[i][j][q] = 0.f;

    const int mrowA0 = wm + ((lane >> 3) & 1) * 8 + (lane & 7);
    const int kcA    = (lane >> 4) & 1;
    const int nrowB0 = wn + ((lane >> 4) & 1) * 8 + (lane & 7);
    const int kcB    = (lane >> 3) & 1;

    issue_loads(0, 0);
    issue_loads(1, 1);

    for (int s = 0; s < 48; s++) {
        const int buf = s % 3;
        if (s + 2 < 48) {
            issue_loads(s + 2, (s + 2) % 3);
            cp_wait<2>();
        } else if (s + 1 < 48) {
            cp_wait<1>();
        } else {
            cp_wait<0>();
        }
        __syncthreads();

        const uint32_t abase = sb + buf * 32768u;
        const uint32_t bbase = abase + 16384u;
#pragma unroll
        for (int k16 = 0; k16 < 4; k16++) {
            uint32_t a[2][4];
#pragma unroll
            for (int i = 0; i < 2; i++) {
                int mr = mrowA0 + 16 * i;
                uint32_t addr = abase + mr * 128 +
                    ((((k16 << 1) | kcA) ^ (mr & 7)) << 4);
                ldmx4(a[i], addr);
            }
            uint32_t b[4][4];
#pragma unroll
            for (int j = 0; j < 4; j++) {
                int nr = nrowB0 + 16 * j;
                uint32_t addr = bbase + nr * 128 +
                    ((((k16 << 1) | kcB) ^ (nr & 7)) << 4);
                ldmx4(b[j], addr);
            }
#pragma unroll
            for (int i = 0; i < 2; i++)
#pragma unroll
                for (int j = 0; j < 4; j++) {
                    mma_bf16(c[i][2 * j],     a[i], b[j][0], b[j][1]);
                    mma_bf16(c[i][2 * j + 1], a[i], b[j][2], b[j][3]);
                }
        }
        __syncthreads();
    }

    const int g = lane >> 2, tig = lane & 3;

    if (fused && z < 2) {
        // RoPE + bf16 hi/lo epilogue for q (z=0) / k (z=1)
        __nv_bfloat16* DhZ = Dh + (size_t)z * QKV_STRIDE;
        __nv_bfloat16* DlZ = Dl + (size_t)z * QKV_STRIDE;
#pragma unroll
        for (int i = 0; i < 2; i++) {
            int mrow = m0 + wm + 16 * i + g;
            int s0 = mrow & 2047, s1 = (mrow + 8) & 2047;
#pragma unroll
            for (int nt = 0; nt < 8; nt++) {
                int col = n0 + wn + nt * 8 + tig * 2;
                int fi = (col & 63) >> 1;
                float cv0 = g_cos[s0 * 32 + fi], sv0 = g_sin[s0 * 32 + fi];
                float cv1 = g_cos[s1 * 32 + fi], sv1 = g_sin[s1 * 32 + fi];
                float r0 = c[i][nt][0] * cv0 - c[i][nt][1] * sv0;
                float r1 = c[i][nt][0] * sv0 + c[i][nt][1] * cv0;
                float r2 = c[i][nt][2] * cv1 - c[i][nt][3] * sv1;
                float r3 = c[i][nt][2] * sv1 + c[i][nt][3] * cv1;
                uint32_t h, l;
                size_t idx0 = (size_t)mrow * 1024 + col;
                split2pack(r0, r1, h, l);
                *reinterpret_cast<uint32_t*>(DhZ + idx0) = h;
                *reinterpret_cast<uint32_t*>(DlZ + idx0) = l;
                size_t idx1 = idx0 + (size_t)8 * 1024;
                split2pack(r2, r3, h, l);
                *reinterpret_cast<uint32_t*>(DhZ + idx1) = h;
                *reinterpret_cast<uint32_t*>(DlZ + idx1) = l;
            }
        }
    } else {
        // fp32 epilogue (V when fused; final projection otherwise)
#pragma unroll
        for (int i = 0; i < 2; i++) {
            int mrow = m0 + wm + 16 * i + g;
#pragma unroll
            for (int nt = 0; nt < 8; nt++) {
                int col = n0 + wn + nt * 8 + tig * 2;
                float* p = Df + (size_t)mrow * 1024 + col;
                *reinterpret_cast<float2*>(p) = make_float2(c[i][nt][0], c[i][nt][1]);
                *reinterpret_cast<float2*>(p + 8 * 1024) = make_float2(c[i][nt][2], c[i][nt][3]);
            }
        }
    }
}

// ---------------------------------------------------------------------------
// Tensor-core causal flash attention, double-buffered K/V.
// BQ=128, BK=64, DH=64. 256 threads = 8 warps x 16 q-rows.
// Output: bf16 hi/lo splits directly to g_ah/g_al ([m][1024]).
// smem: Q hi/lo 32KB + 2 stages x (Kh,Kl,Vth,Vtl = 32KB) = 96KB.
// ---------------------------------------------------------------------------
constexpr int ATT_SMEM = 98304;
constexpr uint32_t QH_O = 0, QL_O = 16384, KV_O = 32768;

__global__ void __launch_bounds__(256, 1)
fattn_tc(const __nv_bfloat16* __restrict__ QKh,
         const __nv_bfloat16* __restrict__ QKl,
         const __nv_bfloat16* __restrict__ Vth,
         const __nv_bfloat16* __restrict__ Vtl,
         __nv_bfloat16* __restrict__ Oh, __nv_bfloat16* __restrict__ Ol)
{
    extern __shared__ char smem[];
    const uint32_t sb = smem_to_u32(smem);
    const int tid = threadIdx.x, lane = tid & 31, w = tid >> 5;
    const int qt = (int)gridDim.x - 1 - (int)blockIdx.x;   // heavy tiles first
    const int bh = blockIdx.y;
    const int b = bh >> 4, h = bh & 15;
    const int q0 = qt * 128;
    const int njk = 2 * qt + 2;

    auto issue_kv = [&](int jk, int buf) {
        uint32_t base = sb + KV_O + buf * 32768u;
#pragma unroll
        for (int i = 0; i < 2; i++) {
            int idx = tid + 256 * i;
            int r = idx >> 3, ch = idx & 7;
            uint32_t sw = r * 128 + ((ch ^ (r & 7)) << 4);
            size_t gk = QKV_STRIDE + (size_t)(b * 2048 + jk * 64 + r) * 1024 + h * 64 + ch * 8;
            cp_async16(base + sw,         QKh + gk);
            cp_async16(base + 8192 + sw,  QKl + gk);
            size_t gv = ((size_t)bh * 64 + r) * 2048 + jk * 64 + ch * 8;
            cp_async16(base + 16384 + sw, Vth + gv);
            cp_async16(base + 24576 + sw, Vtl + gv);
        }
        cp_commit();
    };

    // Q tile (hi/lo)
#pragma unroll
    for (int i = 0; i < 4; i++) {
        int idx = tid + 256 * i;
        int r = idx >> 3, ch = idx & 7;
        size_t gq = (size_t)(b * 2048 + q0 + r) * 1024 + h * 64 + ch * 8;
        uint32_t sw = r * 128 + ((ch ^ (r & 7)) << 4);
        cp_async16(sb + QH_O + sw, QKh + gq);
        cp_async16(sb + QL_O + sw, QKl + gq);
    }
    cp_commit();
    issue_kv(0, 0);
    cp_wait<0>();
    __syncthreads();

    float o[8][4];
#pragma unroll
    for (int nt = 0; nt < 8; nt++)
#pragma unroll
        for (int q = 0; q < 4; q++) o[nt][q] = 0.f;
    float m0 = -1e30f, m1 = -1e30f, l0 = 0.f, l1 = 0.f;

    const int g_  = lane >> 2, tig = lane & 3;
    const int mrA = w * 16 + ((lane >> 3) & 1) * 8 + (lane & 7);
    const int kcA = (lane >> 4) & 1;
    const int nrB = ((lane >> 4) & 1) * 8 + (lane & 7);
    const int kcB = (lane >> 3) & 1;
    const int row0 = q0 + w * 16 + g_;

    for (int jk = 0; jk < njk; jk++) {
        const int buf = jk & 1;
        if (jk + 1 < njk) {
            issue_kv(jk + 1, buf ^ 1);
            cp_wait<1>();
        } else {
            cp_wait<0>();
        }
        __syncthreads();

        const uint32_t kbase = sb + KV_O + buf * 32768u;
        const uint32_t vbase = kbase + 16384u;

        // ---- S = Q K^T (3-term) ----
        float c[8][4];
#pragma unroll
        for (int nt = 0; nt < 8; nt++)
#pragma unroll
            for (int q = 0; q < 4; q++) c[nt][q] = 0.f;

#pragma unroll
        for (int k16 = 0; k16 < 4; k16++) {
            uint32_t ah[4], al[4];
            uint32_t aaddr = sb + QH_O + mrA * 128 +
                ((((k16 << 1) | kcA) ^ (mrA & 7)) << 4);
            ldmx4(ah, aaddr);
            ldmx4(al, aaddr + (QL_O - QH_O));
#pragma unroll
            for (int j = 0; j < 4; j++) {
                int nr = 16 * j + nrB;
                uint32_t baddr = kbase + nr * 128 +
                    ((((k16 << 1) | kcB) ^ (nr & 7)) << 4);
                uint32_t bhh[4], bll[4];
                ldmx4(bhh, baddr);
                ldmx4(bll, baddr + 8192);
                mma_bf16(c[2 * j],     ah, bhh[0], bhh[1]);
                mma_bf16(c[2 * j + 1], ah, bhh[2], bhh[3]);
                mma_bf16(c[2 * j],     al, bhh[0], bhh[1]);
                mma_bf16(c[2 * j + 1], al, bhh[2], bhh[3]);
                mma_bf16(c[2 * j],     ah, bll[0], bll[1]);
                mma_bf16(c[2 * j + 1], ah, bll[2], bll[3]);
            }
        }

        // ---- scale + causal mask ----
#pragma unroll
        for (int nt = 0; nt < 8; nt++)
#pragma unroll
            for (int q = 0; q < 4; q++) c[nt][q] *= 0.125f;

        if (jk >= 2 * qt) {
#pragma unroll
            for (int nt = 0; nt < 8; nt++) {
                int colg = jk * 64 + 8 * nt + 2 * tig;
                if (colg     > row0)     c[nt][0] = -1e30f;
                if (colg + 1 > row0)     c[nt][1] = -1e30f;
                if (colg     > row0 + 8) c[nt][2] = -1e30f;
                if (colg + 1 > row0 + 8) c[nt][3] = -1e30f;
            }
        }

        // ---- online softmax ----
        float rm0 = -1e30f, rm1 = -1e30f;
#pragma unroll
        for (int nt = 0; nt < 8; nt++) {
            rm0 = fmaxf(rm0, fmaxf(c[nt][0], c[nt][1]));
            rm1 = fmaxf(rm1, fmaxf(c[nt][2], c[nt][3]));
        }
        rm0 = fmaxf(rm0, __shfl_xor_sync(0xffffffffu, rm0, 1));
        rm0 = fmaxf(rm0, __shfl_xor_sync(0xffffffffu, rm0, 2));
        rm1 = fmaxf(rm1, __shfl_xor_sync(0xffffffffu, rm1, 1));
        rm1 = fmaxf(rm1, __shfl_xor_sync(0xffffffffu, rm1, 2));

        float mn0 = fmaxf(m0, rm0), mn1 = fmaxf(m1, rm1);
        float a0 = __expf(m0 - mn0), a1 = __expf(m1 - mn1);
        m0 = mn0; m1 = mn1;

        float rs0 = 0.f, rs1 = 0.f;
#pragma unroll
        for (int nt = 0; nt < 8; nt++) {
            c[nt][0] = __expf(c[nt][0] - mn0);
            c[nt][1] = __expf(c[nt][1] - mn0);
            c[nt][2] = __expf(c[nt][2] - mn1);
            c[nt][3] = __expf(c[nt][3] - mn1);
            rs0 += c[nt][0] + c[nt][1];
            rs1 += c[nt][2] + c[nt][3];
        }
        rs0 += __shfl_xor_sync(0xffffffffu, rs0, 1);
        rs0 += __shfl_xor_sync(0xffffffffu, rs0, 2);
        rs1 += __shfl_xor_sync(0xffffffffu, rs1, 1);
        rs1 += __shfl_xor_sync(0xffffffffu, rs1, 2);
        l0 = l0 * a0 + rs0;
        l1 = l1 * a1 + rs1;
#pragma unroll
        for (int nt = 0; nt < 8; nt++) {
            o[nt][0] *= a0; o[nt][1] *= a0;
            o[nt][2] *= a1; o[nt][3] *= a1;
        }

        // ---- O += P V (3-term) ----
#pragma unroll
        for (int k16 = 0; k16 < 4; k16++) {
            uint32_t aph[4], apl[4];
            split2pack(c[2 * k16][0],     c[2 * k16][1],     aph[0], apl[0]);
            split2pack(c[2 * k16][2],     c[2 * k16][3],     aph[1], apl[1]);
            split2pack(c[2 * k16 + 1][0], c[2 * k16 + 1][1], aph[2], apl[2]);
            split2pack(c[2 * k16 + 1][2], c[2 * k16 + 1][3], aph[3], apl[3]);
#pragma unroll
            for (int j = 0; j < 4; j++) {
                int nr = 16 * j + nrB;
                uint32_t baddr = vbase + nr * 128 +
                    ((((k16 << 1) | kcB) ^ (nr & 7)) << 4);
                uint32_t vhh[4], vll[4];
                ldmx4(vhh, baddr);
                ldmx4(vll, baddr + 8192);
                mma_bf16(o[2 * j],     aph, vhh[0], vhh[1]);
                mma_bf16(o[2 * j + 1], aph, vhh[2], vhh[3]);
                mma_bf16(o[2 * j],     apl, vhh[0], vhh[1]);
                mma_bf16(o[2 * j + 1], apl, vhh[2], vhh[3]);
                mma_bf16(o[2 * j],     aph, vll[0], vll[1]);
                mma_bf16(o[2 * j + 1], aph, vll[2], vll[3]);
            }
        }
        __syncthreads();   // all reads of buf done before it is refilled
    }

    // ---- epilogue: write bf16 hi/lo splits ----
    float inv0 = 1.0f / l0, inv1 = 1.0f / l1;
    size_t base0 = (size_t)(b * 2048 + row0) * 1024 + h * 64 + 2 * tig;
    size_t base1 = base0 + (size_t)8 * 1024;
#pragma unroll
    for (int nt = 0; nt < 8; nt++) {
        uint32_t hh, ll;
        split2pack(o[nt][0] * inv0, o[nt][1] * inv0, hh, ll);
        *reinterpret_cast<uint32_t*>(Oh + base0 + 8 * nt) = hh;
        *reinterpret_cast<uint32_t*>(Ol + base0 + 8 * nt) = ll;
        split2pack(o[nt][2] * inv1, o[nt][3] * inv1, hh, ll);
        *reinterpret_cast<uint32_t*>(Oh + base1 + 8 * nt) = hh;
        *reinterpret_cast<uint32_t*>(Ol + base1 + 8 * nt) = ll;
    }
}

// ---------------------------------------------------------------------------
extern "C" void kernel_launch(void* const* d_in, const int* in_sizes, int n_in,
                              void* d_out, int out_size)
{
    (void)in_sizes; (void)n_in; (void)out_size;
    const float* x  = (const float*)d_in[0];
    const float* wq = (const float*)d_in[1];
    const float* wk = (const float*)d_in[2];
    const float* wv = (const float*)d_in[3];
    const float* wo = (const float*)d_in[4];
    float* out = (float*)d_out;

    float* pv;
    __nv_bfloat16 *pah, *pal, *pwh, *pwl, *pqkh, *pqkl, *pvth, *pvtl;
    cudaGetSymbolAddress((void**)&pv,   g_v);
    cudaGetSymbolAddress((void**)&pah,  g_ah);
    cudaGetSymbolAddress((void**)&pal,  g_al);
    cudaGetSymbolAddress((void**)&pwh,  g_wh);
    cudaGetSymbolAddress((void**)&pwl,  g_wl);
    cudaGetSymbolAddress((void**)&pqkh, g_qkh);
    cudaGetSymbolAddress((void**)&pqkl, g_qkl);
    cudaGetSymbolAddress((void**)&pvth, g_vth);
    cudaGetSymbolAddress((void**)&pvtl, g_vtl);

    cudaFuncSetAttribute(gemm_bf3, cudaFuncAttributeMaxDynamicSharedMemorySize, GEMM_SMEM);
    cudaFuncSetAttribute(fattn_tc, cudaFuncAttributeMaxDynamicSharedMemorySize, ATT_SMEM);

    const int n4x = M_TOT * D_ / 4;      // 2097152
    const int n4w = D_ * D_ / 4;         // 262144

    rope_table_kernel<<<(S_ * 32) / 256, 256>>>();
    split_kernel<<<n4x / 256, 256>>>(x,  pah, pal, n4x);
    split_kernel<<<n4w / 256, 256>>>(wq, pwh + 0 * W_STRIDE, pwl + 0 * W_STRIDE, n4w);
    split_kernel<<<n4w / 256, 256>>>(wk, pwh + 1 * W_STRIDE, pwl + 1 * W_STRIDE, n4w);
    split_kernel<<<n4w / 256, 256>>>(wv, pwh + 2 * W_STRIDE, pwl + 2 * W_STRIDE, n4w);
    split_kernel<<<n4w / 256, 256>>>(wo, pwh + 3 * W_STRIDE, pwl + 3 * W_STRIDE, n4w);

    // Fused QKV projection: z=0,1 -> RoPE'd bf16 q/k; z=2 -> fp32 v
    gemm_bf3<<<dim3(8, 64, 3), 256, GEMM_SMEM>>>(pah, pal, pwh, pwl,
                                                 pv, pqkh, pqkl, 1);

    vtrans_kernel<<<dim3(64, 2, 64), 256>>>(pv, pvth, pvtl);

    // Attention: writes bf16 hi/lo splits straight into pah/pal
    fattn_tc<<<dim3(16, 64), 256, ATT_SMEM>>>(pqkh, pqkl, pvth, pvtl, pah, pal);

    // Output projection (wo = weight index 3), fp32 out
    gemm_bf3<<<dim3(8, 64, 1), 256, GEMM_SMEM>>>(pah, pal,
        pwh + 3 * W_STRIDE, pwl + 3 * W_STRIDE, out, nullptr, nullptr, 0);
}

// round 6
// speedup vs baseline: 3.5085x; 1.0299x over previous
#include <cuda_runtime.h>
#include <cuda_bf16.h>
#include <cstdint>

// ---------------------------------------------------------------------------
// Problem constants
// ---------------------------------------------------------------------------
constexpr int B_  = 4;
constexpr int S_  = 2048;
constexpr int D_  = 1024;
constexpr int H_  = 16;
constexpr int DH_ = 64;
constexpr int M_TOT = B_ * S_;                    // 8192
constexpr size_t QKV_STRIDE = (size_t)M_TOT * D_; // 8388608
constexpr size_t W_STRIDE   = (size_t)D_ * D_;    // 1048576

// Scratch (device globals: allocation-free rule)
__device__ float g_v[M_TOT * D_];                 // fp32 V (pre-transpose)
__device__ float g_cos[S_ * (DH_ / 2)];
__device__ float g_sin[S_ * (DH_ / 2)];
__device__ __nv_bfloat16 g_ah[M_TOT * D_];        // hi split: x, later attention out
__device__ __nv_bfloat16 g_al[M_TOT * D_];        // lo split
__device__ __nv_bfloat16 g_wh[4 * W_STRIDE];      // hi split of wq|wk|wv|wo
__device__ __nv_bfloat16 g_wl[4 * W_STRIDE];      // lo split
__device__ __nv_bfloat16 g_qkh[2 * M_TOT * D_];   // hi split of roped q|k
__device__ __nv_bfloat16 g_qkl[2 * M_TOT * D_];   // lo split
__device__ __nv_bfloat16 g_vth[M_TOT * D_];       // V^T hi: [bh][d][s]
__device__ __nv_bfloat16 g_vtl[M_TOT * D_];       // V^T lo

// ---------------------------------------------------------------------------
// helpers
// ---------------------------------------------------------------------------
__device__ __forceinline__ uint32_t smem_to_u32(const void* smem_ptr) {
    uint32_t addr;
    asm("{ .reg .u64 tmp; cvta.to.shared.u64 tmp, %1; cvt.u32.u64 %0, tmp; }"
        : "=r"(addr) : "l"(smem_ptr));
    return addr;
}

__device__ __forceinline__ void cp_async16(uint32_t saddr, const void* gptr) {
    asm volatile("cp.async.cg.shared.global [%0], [%1], 16;"
                 :: "r"(saddr), "l"(gptr) : "memory");
}
__device__ __forceinline__ void cp_commit() {
    asm volatile("cp.async.commit_group;" ::: "memory");
}
template <int N>
__device__ __forceinline__ void cp_wait() {
    asm volatile("cp.async.wait_group %0;" :: "n"(N) : "memory");
}

__device__ __forceinline__ void ldmx4(uint32_t* r, uint32_t addr) {
    asm volatile("ldmatrix.sync.aligned.m8n8.x4.shared.b16 {%0,%1,%2,%3}, [%4];"
                 : "=r"(r[0]), "=r"(r[1]), "=r"(r[2]), "=r"(r[3]) : "r"(addr));
}

__device__ __forceinline__ void mma_bf16(float* c, const uint32_t* a,
                                         uint32_t b0, uint32_t b1) {
    asm volatile(
        "mma.sync.aligned.m16n8k16.row.col.f32.bf16.bf16.f32 "
        "{%0,%1,%2,%3}, {%4,%5,%6,%7}, {%8,%9}, {%0,%1,%2,%3};"
        : "+f"(c[0]), "+f"(c[1]), "+f"(c[2]), "+f"(c[3])
        : "r"(a[0]), "r"(a[1]), "r"(a[2]), "r"(a[3]), "r"(b0), "r"(b1));
}

__device__ __forceinline__ uint32_t pack2bf(__nv_bfloat16 a, __nv_bfloat16 b) {
    return (uint32_t)__bfloat16_as_ushort(a) | ((uint32_t)__bfloat16_as_ushort(b) << 16);
}

__device__ __forceinline__ void split2pack(float x, float y, uint32_t& h, uint32_t& l) {
    __nv_bfloat16 hx = __float2bfloat16(x), hy = __float2bfloat16(y);
    __nv_bfloat16 lx = __float2bfloat16(x - __bfloat162float(hx));
    __nv_bfloat16 ly = __float2bfloat16(y - __bfloat162float(hy));
    h = pack2bf(hx, hy);
    l = pack2bf(lx, ly);
}

// ---------------------------------------------------------------------------
// Split fp32 -> (hi, lo) bf16
// ---------------------------------------------------------------------------
__global__ void split_kernel(const float* __restrict__ src,
                             __nv_bfloat16* __restrict__ hi,
                             __nv_bfloat16* __restrict__ lo, int n4)
{
    int i = blockIdx.x * 256 + threadIdx.x;
    if (i >= n4) return;
    float4 v = reinterpret_cast<const float4*>(src)[i];
    uint32_t h0, l0, h1, l1;
    split2pack(v.x, v.y, h0, l0);
    split2pack(v.z, v.w, h1, l1);
    reinterpret_cast<uint2*>(hi)[i] = make_uint2(h0, h1);
    reinterpret_cast<uint2*>(lo)[i] = make_uint2(l0, l1);
}

// ---------------------------------------------------------------------------
// V transpose + split: v[b*2048+s][h*64+d] -> vt[bh][d][s] (hi/lo bf16)
// ---------------------------------------------------------------------------
__global__ void vtrans_kernel(const float* __restrict__ v,
                              __nv_bfloat16* __restrict__ vth,
                              __nv_bfloat16* __restrict__ vtl)
{
    __shared__ float t[32][33];
    const int st = blockIdx.x, dt = blockIdx.y, bh = blockIdx.z;
    const int b = bh >> 4, h = bh & 15;
    const int lx = threadIdx.x & 31, ly = threadIdx.x >> 5;
#pragma unroll
    for (int i = 0; i < 4; i++) {
        int s = st * 32 + ly + 8 * i;
        t[ly + 8 * i][lx] = v[(size_t)(b * 2048 + s) * 1024 + h * 64 + dt * 32 + lx];
    }
    __syncthreads();
#pragma unroll
    for (int i = 0; i < 4; i++) {
        int d = dt * 32 + ly + 8 * i;
        float val = t[lx][ly + 8 * i];
        __nv_bfloat16 hi = __float2bfloat16(val);
        __nv_bfloat16 lo = __float2bfloat16(val - __bfloat162float(hi));
        size_t idx = ((size_t)bh * 64 + d) * 2048 + st * 32 + lx;
        vth[idx] = hi;
        vtl[idx] = lo;
    }
}

// ---------------------------------------------------------------------------
// RoPE cos/sin table
// ---------------------------------------------------------------------------
__global__ void rope_table_kernel()
{
    int idx = blockIdx.x * 256 + threadIdx.x;   // 65536
    int s = idx >> 5, i = idx & 31;
    double inv = exp(-((double)(2 * i) / 64.0) * log(10000.0));
    float  angf = (float)s * (float)inv;
    double ang  = (double)angf;
    g_cos[idx] = (float)cos(ang);
    g_sin[idx] = (float)sin(ang);
}

// ---------------------------------------------------------------------------
// bf16 mma.sync GEMM, fused 3-term fp32 emulation.
// Per k32-step: load Ah/Al/Wh/Wl tiles once, issue hi*hi + lo*hi + hi*lo MMAs
// from registers. BM=BN=128, BK=32, 32 k-steps, 3-stage cp.async ring.
// smem rows are 64B (4 x 16B chunks); conflict-free swizzle ch ^ ((r>>1)&3).
// fused=1 (QKV): z=0,1 -> RoPE epilogue -> bf16 hi/lo; z=2 -> fp32 (V).
// fused=0: fp32 epilogue (final projection).
// ---------------------------------------------------------------------------
constexpr int GEMM_SMEM = 98304;   // 3 stages * 32KB (Ah 8K | Al 8K | Bh 8K | Bl 8K)

__global__ void __launch_bounds__(256, 2)
gemm_bf3(const __nv_bfloat16* __restrict__ Ah, const __nv_bfloat16* __restrict__ Al,
         const __nv_bfloat16* __restrict__ Wh, const __nv_bfloat16* __restrict__ Wl,
         float* __restrict__ Df, __nv_bfloat16* __restrict__ Dh,
         __nv_bfloat16* __restrict__ Dl, int fused)
{
    extern __shared__ char smem[];
    const uint32_t sb = smem_to_u32(smem);
    const int tid = threadIdx.x, lane = tid & 31, wid = tid >> 5;
    const int z = blockIdx.z;
    const __nv_bfloat16* WhZ = Wh + (size_t)z * W_STRIDE;
    const __nv_bfloat16* WlZ = Wl + (size_t)z * W_STRIDE;
    const int m0 = blockIdx.y * 128, n0 = blockIdx.x * 128;
    const int wm = (wid >> 1) * 32, wn = (wid & 1) * 64;

    auto issue_loads = [&](int s, int buf) {
        const int k0 = s * 32;
        uint32_t base = sb + buf * 32768u;
#pragma unroll
        for (int i = 0; i < 2; i++) {
            int idx = tid + 256 * i;
            int row = idx >> 2, ch = idx & 3;
            uint32_t sw = (uint32_t)row * 64 + ((uint32_t)(ch ^ ((row >> 1) & 3)) << 4);
            size_t ga = (size_t)(m0 + row) * 1024 + k0 + ch * 8;
            size_t gb = (size_t)(n0 + row) * 1024 + k0 + ch * 8;
            cp_async16(base + sw,          Ah  + ga);
            cp_async16(base + 8192 + sw,   Al  + ga);
            cp_async16(base + 16384 + sw,  WhZ + gb);
            cp_async16(base + 24576 + sw,  WlZ + gb);
        }
        cp_commit();
    };

    float c[2][8][4];
#pragma unroll
    for (int i = 0; i < 2; i++)
#pragma unroll
        for (int j = 0; j < 8; j++)
#pragma unroll
            for (int q = 0; q < 4; q++) c[i][j][q] = 0.f;

    const int mrowA0 = wm + ((lane >> 3) & 1) * 8 + (lane & 7);
    const int kcA    = (lane >> 4) & 1;
    const int nrowB0 = wn + ((lane >> 4) & 1) * 8 + (lane & 7);
    const int kcB    = (lane >> 3) & 1;

    issue_loads(0, 0);
    issue_loads(1, 1);

    for (int s = 0; s < 32; s++) {
        const int buf = s % 3;
        if (s + 2 < 32) {
            issue_loads(s + 2, (s + 2) % 3);
            cp_wait<2>();
        } else if (s + 1 < 32) {
            cp_wait<1>();
        } else {
            cp_wait<0>();
        }
        __syncthreads();

        const uint32_t abase = sb + buf * 32768u;
        const uint32_t bbase = abase + 16384u;
#pragma unroll
        for (int kc2 = 0; kc2 < 2; kc2++) {
            uint32_t ah[2][4], al[2][4];
#pragma unroll
            for (int i = 0; i < 2; i++) {
                int mr = mrowA0 + 16 * i;
                int unit = (kc2 << 1) | kcA;
                uint32_t addr = abase + mr * 64 +
                    ((uint32_t)(unit ^ ((mr >> 1) & 3)) << 4);
                ldmx4(ah[i], addr);
                ldmx4(al[i], addr + 8192);
            }
#pragma unroll
            for (int j = 0; j < 4; j++) {
                int nr = nrowB0 + 16 * j;
                int unit = (kc2 << 1) | kcB;
                uint32_t baddr = bbase + nr * 64 +
                    ((uint32_t)(unit ^ ((nr >> 1) & 3)) << 4);
                uint32_t bh[4], bl[4];
                ldmx4(bh, baddr);
                ldmx4(bl, baddr + 8192);
#pragma unroll
                for (int i = 0; i < 2; i++) {
                    mma_bf16(c[i][2 * j],     ah[i], bh[0], bh[1]);
                    mma_bf16(c[i][2 * j + 1], ah[i], bh[2], bh[3]);
                    mma_bf16(c[i][2 * j],     al[i], bh[0], bh[1]);
                    mma_bf16(c[i][2 * j + 1], al[i], bh[2], bh[3]);
                    mma_bf16(c[i][2 * j],     ah[i], bl[0], bl[1]);
                    mma_bf16(c[i][2 * j + 1], ah[i], bl[2], bl[3]);
                }
            }
        }
        __syncthreads();
    }

    const int g = lane >> 2, tig = lane & 3;

    if (fused && z < 2) {
        // RoPE + bf16 hi/lo epilogue for q (z=0) / k (z=1)
        __nv_bfloat16* DhZ = Dh + (size_t)z * QKV_STRIDE;
        __nv_bfloat16* DlZ = Dl + (size_t)z * QKV_STRIDE;
#pragma unroll
        for (int i = 0; i < 2; i++) {
            int mrow = m0 + wm + 16 * i + g;
            int s0 = mrow & 2047, s1 = (mrow + 8) & 2047;
#pragma unroll
            for (int nt = 0; nt < 8; nt++) {
                int col = n0 + wn + nt * 8 + tig * 2;
                int fi = (col & 63) >> 1;
                float cv0 = g_cos[s0 * 32 + fi], sv0 = g_sin[s0 * 32 + fi];
                float cv1 = g_cos[s1 * 32 + fi], sv1 = g_sin[s1 * 32 + fi];
                float r0 = c[i][nt][0] * cv0 - c[i][nt][1] * sv0;
                float r1 = c[i][nt][0] * sv0 + c[i][nt][1] * cv0;
                float r2 = c[i][nt][2] * cv1 - c[i][nt][3] * sv1;
                float r3 = c[i][nt][2] * sv1 + c[i][nt][3] * cv1;
                uint32_t h, l;
                size_t idx0 = (size_t)mrow * 1024 + col;
                split2pack(r0, r1, h, l);
                *reinterpret_cast<uint32_t*>(DhZ + idx0) = h;
                *reinterpret_cast<uint32_t*>(DlZ + idx0) = l;
                size_t idx1 = idx0 + (size_t)8 * 1024;
                split2pack(r2, r3, h, l);
                *reinterpret_cast<uint32_t*>(DhZ + idx1) = h;
                *reinterpret_cast<uint32_t*>(DlZ + idx1) = l;
            }
        }
    } else {
        // fp32 epilogue (V when fused; final projection otherwise)
#pragma unroll
        for (int i = 0; i < 2; i++) {
            int mrow = m0 + wm + 16 * i + g;
#pragma unroll
            for (int nt = 0; nt < 8; nt++) {
                int col = n0 + wn + nt * 8 + tig * 2;
                float* p = Df + (size_t)mrow * 1024 + col;
                *reinterpret_cast<float2*>(p) = make_float2(c[i][nt][0], c[i][nt][1]);
                *reinterpret_cast<float2*>(p + 8 * 1024) = make_float2(c[i][nt][2], c[i][nt][3]);
            }
        }
    }
}

// ---------------------------------------------------------------------------
// Tensor-core causal flash attention, double-buffered K/V (unchanged R5).
// ---------------------------------------------------------------------------
constexpr int ATT_SMEM = 98304;
constexpr uint32_t QH_O = 0, QL_O = 16384, KV_O = 32768;

__global__ void __launch_bounds__(256, 1)
fattn_tc(const __nv_bfloat16* __restrict__ QKh,
         const __nv_bfloat16* __restrict__ QKl,
         const __nv_bfloat16* __restrict__ Vth,
         const __nv_bfloat16* __restrict__ Vtl,
         __nv_bfloat16* __restrict__ Oh, __nv_bfloat16* __restrict__ Ol)
{
    extern __shared__ char smem[];
    const uint32_t sb = smem_to_u32(smem);
    const int tid = threadIdx.x, lane = tid & 31, w = tid >> 5;
    const int qt = (int)gridDim.x - 1 - (int)blockIdx.x;
    const int bh = blockIdx.y;
    const int b = bh >> 4, h = bh & 15;
    const int q0 = qt * 128;
    const int njk = 2 * qt + 2;

    auto issue_kv = [&](int jk, int buf) {
        uint32_t base = sb + KV_O + buf * 32768u;
#pragma unroll
        for (int i = 0; i < 2; i++) {
            int idx = tid + 256 * i;
            int r = idx >> 3, ch = idx & 7;
            uint32_t sw = r * 128 + ((ch ^ (r & 7)) << 4);
            size_t gk = QKV_STRIDE + (size_t)(b * 2048 + jk * 64 + r) * 1024 + h * 64 + ch * 8;
            cp_async16(base + sw,         QKh + gk);
            cp_async16(base + 8192 + sw,  QKl + gk);
            size_t gv = ((size_t)bh * 64 + r) * 2048 + jk * 64 + ch * 8;
            cp_async16(base + 16384 + sw, Vth + gv);
            cp_async16(base + 24576 + sw, Vtl + gv);
        }
        cp_commit();
    };

#pragma unroll
    for (int i = 0; i < 4; i++) {
        int idx = tid + 256 * i;
        int r = idx >> 3, ch = idx & 7;
        size_t gq = (size_t)(b * 2048 + q0 + r) * 1024 + h * 64 + ch * 8;
        uint32_t sw = r * 128 + ((ch ^ (r & 7)) << 4);
        cp_async16(sb + QH_O + sw, QKh + gq);
        cp_async16(sb + QL_O + sw, QKl + gq);
    }
    cp_commit();
    issue_kv(0, 0);
    cp_wait<0>();
    __syncthreads();

    float o[8][4];
#pragma unroll
    for (int nt = 0; nt < 8; nt++)
#pragma unroll
        for (int q = 0; q < 4; q++) o[nt][q] = 0.f;
    float m0 = -1e30f, m1 = -1e30f, l0 = 0.f, l1 = 0.f;

    const int g_  = lane >> 2, tig = lane & 3;
    const int mrA = w * 16 + ((lane >> 3) & 1) * 8 + (lane & 7);
    const int kcA = (lane >> 4) & 1;
    const int nrB = ((lane >> 4) & 1) * 8 + (lane & 7);
    const int kcB = (lane >> 3) & 1;
    const int row0 = q0 + w * 16 + g_;

    for (int jk = 0; jk < njk; jk++) {
        const int buf = jk & 1;
        if (jk + 1 < njk) {
            issue_kv(jk + 1, buf ^ 1);
            cp_wait<1>();
        } else {
            cp_wait<0>();
        }
        __syncthreads();

        const uint32_t kbase = sb + KV_O + buf * 32768u;
        const uint32_t vbase = kbase + 16384u;

        float c[8][4];
#pragma unroll
        for (int nt = 0; nt < 8; nt++)
#pragma unroll
            for (int q = 0; q < 4; q++) c[nt][q] = 0.f;

#pragma unroll
        for (int k16 = 0; k16 < 4; k16++) {
            uint32_t ah[4], al[4];
            uint32_t aaddr = sb + QH_O + mrA * 128 +
                ((((k16 << 1) | kcA) ^ (mrA & 7)) << 4);
            ldmx4(ah, aaddr);
            ldmx4(al, aaddr + (QL_O - QH_O));
#pragma unroll
            for (int j = 0; j < 4; j++) {
                int nr = 16 * j + nrB;
                uint32_t baddr = kbase + nr * 128 +
                    ((((k16 << 1) | kcB) ^ (nr & 7)) << 4);
                uint32_t bhh[4], bll[4];
                ldmx4(bhh, baddr);
                ldmx4(bll, baddr + 8192);
                mma_bf16(c[2 * j],     ah, bhh[0], bhh[1]);
                mma_bf16(c[2 * j + 1], ah, bhh[2], bhh[3]);
                mma_bf16(c[2 * j],     al, bhh[0], bhh[1]);
                mma_bf16(c[2 * j + 1], al, bhh[2], bhh[3]);
                mma_bf16(c[2 * j],     ah, bll[0], bll[1]);
                mma_bf16(c[2 * j + 1], ah, bll[2], bll[3]);
            }
        }

#pragma unroll
        for (int nt = 0; nt < 8; nt++)
#pragma unroll
            for (int q = 0; q < 4; q++) c[nt][q] *= 0.125f;

        if (jk >= 2 * qt) {
#pragma unroll
            for (int nt = 0; nt < 8; nt++) {
                int colg = jk * 64 + 8 * nt + 2 * tig;
                if (colg     > row0)     c[nt][0] = -1e30f;
                if (colg + 1 > row0)     c[nt][1] = -1e30f;
                if (colg     > row0 + 8) c[nt][2] = -1e30f;
                if (colg + 1 > row0 + 8) c[nt][3] = -1e30f;
            }
        }

        float rm0 = -1e30f, rm1 = -1e30f;
#pragma unroll
        for (int nt = 0; nt < 8; nt++) {
            rm0 = fmaxf(rm0, fmaxf(c[nt][0], c[nt][1]));
            rm1 = fmaxf(rm1, fmaxf(c[nt][2], c[nt][3]));
        }
        rm0 = fmaxf(rm0, __shfl_xor_sync(0xffffffffu, rm0, 1));
        rm0 = fmaxf(rm0, __shfl_xor_sync(0xffffffffu, rm0, 2));
        rm1 = fmaxf(rm1, __shfl_xor_sync(0xffffffffu, rm1, 1));
        rm1 = fmaxf(rm1, __shfl_xor_sync(0xffffffffu, rm1, 2));

        float mn0 = fmaxf(m0, rm0), mn1 = fmaxf(m1, rm1);
        float a0 = __expf(m0 - mn0), a1 = __expf(m1 - mn1);
        m0 = mn0; m1 = mn1;

        float rs0 = 0.f, rs1 = 0.f;
#pragma unroll
        for (int nt = 0; nt < 8; nt++) {
            c[nt][0] = __expf(c[nt][0] - mn0);
            c[nt][1] = __expf(c[nt][1] - mn0);
            c[nt][2] = __expf(c[nt][2] - mn1);
            c[nt][3] = __expf(c[nt][3] - mn1);
            rs0 += c[nt][0] + c[nt][1];
            rs1 += c[nt][2] + c[nt][3];
        }
        rs0 += __shfl_xor_sync(0xffffffffu, rs0, 1);
        rs0 += __shfl_xor_sync(0xffffffffu, rs0, 2);
        rs1 += __shfl_xor_sync(0xffffffffu, rs1, 1);
        rs1 += __shfl_xor_sync(0xffffffffu, rs1, 2);
        l0 = l0 * a0 + rs0;
        l1 = l1 * a1 + rs1;
#pragma unroll
        for (int nt = 0; nt < 8; nt++) {
            o[nt][0] *= a0; o[nt][1] *= a0;
            o[nt][2] *= a1; o[nt][3] *= a1;
        }

#pragma unroll
        for (int k16 = 0; k16 < 4; k16++) {
            uint32_t aph[4], apl[4];
            split2pack(c[2 * k16][0],     c[2 * k16][1],     aph[0], apl[0]);
            split2pack(c[2 * k16][2],     c[2 * k16][3],     aph[1], apl[1]);
            split2pack(c[2 * k16 + 1][0], c[2 * k16 + 1][1], aph[2], apl[2]);
            split2pack(c[2 * k16 + 1][2], c[2 * k16 + 1][3], aph[3], apl[3]);
#pragma unroll
            for (int j = 0; j < 4; j++) {
                int nr = 16 * j + nrB;
                uint32_t baddr = vbase + nr * 128 +
                    ((((k16 << 1) | kcB) ^ (nr & 7)) << 4);
                uint32_t vhh[4], vll[4];
                ldmx4(vhh, baddr);
                ldmx4(vll, baddr + 8192);
                mma_bf16(o[2 * j],     aph, vhh[0], vhh[1]);
                mma_bf16(o[2 * j + 1], aph, vhh[2], vhh[3]);
                mma_bf16(o[2 * j],     apl, vhh[0], vhh[1]);
                mma_bf16(o[2 * j + 1], apl, vhh[2], vhh[3]);
                mma_bf16(o[2 * j],     aph, vll[0], vll[1]);
                mma_bf16(o[2 * j + 1], aph, vll[2], vll[3]);
            }
        }
        __syncthreads();
    }

    float inv0 = 1.0f / l0, inv1 = 1.0f / l1;
    size_t base0 = (size_t)(b * 2048 + row0) * 1024 + h * 64 + 2 * tig;
    size_t base1 = base0 + (size_t)8 * 1024;
#pragma unroll
    for (int nt = 0; nt < 8; nt++) {
        uint32_t hh, ll;
        split2pack(o[nt][0] * inv0, o[nt][1] * inv0, hh, ll);
        *reinterpret_cast<uint32_t*>(Oh + base0 + 8 * nt) = hh;
        *reinterpret_cast<uint32_t*>(Ol + base0 + 8 * nt) = ll;
        split2pack(o[nt][2] * inv1, o[nt][3] * inv1, hh, ll);
        *reinterpret_cast<uint32_t*>(Oh + base1 + 8 * nt) = hh;
        *reinterpret_cast<uint32_t*>(Ol + base1 + 8 * nt) = ll;
    }
}

// ---------------------------------------------------------------------------
extern "C" void kernel_launch(void* const* d_in, const int* in_sizes, int n_in,
                              void* d_out, int out_size)
{
    (void)in_sizes; (void)n_in; (void)out_size;
    const float* x  = (const float*)d_in[0];
    const float* wq = (const float*)d_in[1];
    const float* wk = (const float*)d_in[2];
    const float* wv = (const float*)d_in[3];
    const float* wo = (const float*)d_in[4];
    float* out = (float*)d_out;

    float* pv;
    __nv_bfloat16 *pah, *pal, *pwh, *pwl, *pqkh, *pqkl, *pvth, *pvtl;
    cudaGetSymbolAddress((void**)&pv,   g_v);
    cudaGetSymbolAddress((void**)&pah,  g_ah);
    cudaGetSymbolAddress((void**)&pal,  g_al);
    cudaGetSymbolAddress((void**)&pwh,  g_wh);
    cudaGetSymbolAddress((void**)&pwl,  g_wl);
    cudaGetSymbolAddress((void**)&pqkh, g_qkh);
    cudaGetSymbolAddress((void**)&pqkl, g_qkl);
    cudaGetSymbolAddress((void**)&pvth, g_vth);
    cudaGetSymbolAddress((void**)&pvtl, g_vtl);

    cudaFuncSetAttribute(gemm_bf3, cudaFuncAttributeMaxDynamicSharedMemorySize, GEMM_SMEM);
    cudaFuncSetAttribute(fattn_tc, cudaFuncAttributeMaxDynamicSharedMemorySize, ATT_SMEM);

    const int n4x = M_TOT * D_ / 4;      // 2097152
    const int n4w = D_ * D_ / 4;         // 262144

    rope_table_kernel<<<(S_ * 32) / 256, 256>>>();
    split_kernel<<<n4x / 256, 256>>>(x,  pah, pal, n4x);
    split_kernel<<<n4w / 256, 256>>>(wq, pwh + 0 * W_STRIDE, pwl + 0 * W_STRIDE, n4w);
    split_kernel<<<n4w / 256, 256>>>(wk, pwh + 1 * W_STRIDE, pwl + 1 * W_STRIDE, n4w);
    split_kernel<<<n4w / 256, 256>>>(wv, pwh + 2 * W_STRIDE, pwl + 2 * W_STRIDE, n4w);
    split_kernel<<<n4w / 256, 256>>>(wo, pwh + 3 * W_STRIDE, pwl + 3 * W_STRIDE, n4w);

    // Fused QKV projection: z=0,1 -> RoPE'd bf16 q/k; z=2 -> fp32 v
    gemm_bf3<<<dim3(8, 64, 3), 256, GEMM_SMEM>>>(pah, pal, pwh, pwl,
                                                 pv, pqkh, pqkl, 1);

    vtrans_kernel<<<dim3(64, 2, 64), 256>>>(pv, pvth, pvtl);

    // Attention: writes bf16 hi/lo splits straight into pah/pal
    fattn_tc<<<dim3(16, 64), 256, ATT_SMEM>>>(pqkh, pqkl, pvth, pvtl, pah, pal);

    // Output projection (wo = weight index 3), fp32 out
    gemm_bf3<<<dim3(8, 64, 1), 256, GEMM_SMEM>>>(pah, pal,
        pwh + 3 * W_STRIDE, pwl + 3 * W_STRIDE, out, nullptr, nullptr, 0);
}

// round 7
// speedup vs baseline: 3.5722x; 1.0182x over previous
#include <cuda_runtime.h>
#include <cuda_bf16.h>
#include <cstdint>

// ---------------------------------------------------------------------------
// Problem constants
// ---------------------------------------------------------------------------
constexpr int B_  = 4;
constexpr int S_  = 2048;
constexpr int D_  = 1024;
constexpr int H_  = 16;
constexpr int DH_ = 64;
constexpr int M_TOT = B_ * S_;                    // 8192
constexpr size_t QKV_STRIDE = (size_t)M_TOT * D_; // 8388608
constexpr size_t W_STRIDE   = (size_t)D_ * D_;    // 1048576

// Scratch (device globals: allocation-free rule)
__device__ float g_v[M_TOT * D_];                 // fp32 V (pre-transpose)
__device__ float g_cos[S_ * (DH_ / 2)];
__device__ float g_sin[S_ * (DH_ / 2)];
__device__ __nv_bfloat16 g_ah[M_TOT * D_];        // hi split: x, later attention out
__device__ __nv_bfloat16 g_al[M_TOT * D_];        // lo split
__device__ __nv_bfloat16 g_wh[4 * W_STRIDE];      // hi split of wq|wk|wv|wo
__device__ __nv_bfloat16 g_wl[4 * W_STRIDE];      // lo split
__device__ __nv_bfloat16 g_qkh[2 * M_TOT * D_];   // hi split of roped q|k
__device__ __nv_bfloat16 g_qkl[2 * M_TOT * D_];   // lo split
__device__ __nv_bfloat16 g_vth[M_TOT * D_];       // V^T hi: [bh][d][s]
__device__ __nv_bfloat16 g_vtl[M_TOT * D_];       // V^T lo

// ---------------------------------------------------------------------------
// helpers
// ---------------------------------------------------------------------------
__device__ __forceinline__ uint32_t smem_to_u32(const void* smem_ptr) {
    uint32_t addr;
    asm("{ .reg .u64 tmp; cvta.to.shared.u64 tmp, %1; cvt.u32.u64 %0, tmp; }"
        : "=r"(addr) : "l"(smem_ptr));
    return addr;
}

__device__ __forceinline__ void cp_async16(uint32_t saddr, const void* gptr) {
    asm volatile("cp.async.cg.shared.global [%0], [%1], 16;"
                 :: "r"(saddr), "l"(gptr) : "memory");
}
__device__ __forceinline__ void cp_commit() {
    asm volatile("cp.async.commit_group;" ::: "memory");
}
template <int N>
__device__ __forceinline__ void cp_wait() {
    asm volatile("cp.async.wait_group %0;" :: "n"(N) : "memory");
}

__device__ __forceinline__ void ldmx4(uint32_t* r, uint32_t addr) {
    asm volatile("ldmatrix.sync.aligned.m8n8.x4.shared.b16 {%0,%1,%2,%3}, [%4];"
                 : "=r"(r[0]), "=r"(r[1]), "=r"(r[2]), "=r"(r[3]) : "r"(addr));
}

__device__ __forceinline__ void mma_bf16(float* c, const uint32_t* a,
                                         uint32_t b0, uint32_t b1) {
    asm volatile(
        "mma.sync.aligned.m16n8k16.row.col.f32.bf16.bf16.f32 "
        "{%0,%1,%2,%3}, {%4,%5,%6,%7}, {%8,%9}, {%0,%1,%2,%3};"
        : "+f"(c[0]), "+f"(c[1]), "+f"(c[2]), "+f"(c[3])
        : "r"(a[0]), "r"(a[1]), "r"(a[2]), "r"(a[3]), "r"(b0), "r"(b1));
}

__device__ __forceinline__ uint32_t pack2bf(__nv_bfloat16 a, __nv_bfloat16 b) {
    return (uint32_t)__bfloat16_as_ushort(a) | ((uint32_t)__bfloat16_as_ushort(b) << 16);
}

__device__ __forceinline__ void split2pack(float x, float y, uint32_t& h, uint32_t& l) {
    __nv_bfloat16 hx = __float2bfloat16(x), hy = __float2bfloat16(y);
    __nv_bfloat16 lx = __float2bfloat16(x - __bfloat162float(hx));
    __nv_bfloat16 ly = __float2bfloat16(y - __bfloat162float(hy));
    h = pack2bf(hx, hy);
    l = pack2bf(lx, ly);
}

// ---------------------------------------------------------------------------
// Split fp32 -> (hi, lo) bf16
// ---------------------------------------------------------------------------
__global__ void split_kernel(const float* __restrict__ src,
                             __nv_bfloat16* __restrict__ hi,
                             __nv_bfloat16* __restrict__ lo, int n4)
{
    int i = blockIdx.x * 256 + threadIdx.x;
    if (i >= n4) return;
    float4 v = reinterpret_cast<const float4*>(src)[i];
    uint32_t h0, l0, h1, l1;
    split2pack(v.x, v.y, h0, l0);
    split2pack(v.z, v.w, h1, l1);
    reinterpret_cast<uint2*>(hi)[i] = make_uint2(h0, h1);
    reinterpret_cast<uint2*>(lo)[i] = make_uint2(l0, l1);
}

// Fused split of the 4 weight matrices (wq|wk|wv|wo contiguous targets)
__global__ void wsplit_kernel(const float* __restrict__ w0, const float* __restrict__ w1,
                              const float* __restrict__ w2, const float* __restrict__ w3,
                              __nv_bfloat16* __restrict__ hi,
                              __nv_bfloat16* __restrict__ lo)
{
    const int n4w = (int)(W_STRIDE / 4);
    int i = blockIdx.x * 256 + threadIdx.x;   // 0 .. 4*n4w-1
    int z = i / n4w, r = i - z * n4w;
    const float* src = (z == 0) ? w0 : (z == 1) ? w1 : (z == 2) ? w2 : w3;
    float4 v = reinterpret_cast<const float4*>(src)[r];
    uint32_t h0, l0, h1, l1;
    split2pack(v.x, v.y, h0, l0);
    split2pack(v.z, v.w, h1, l1);
    reinterpret_cast<uint2*>(hi)[i] = make_uint2(h0, h1);
    reinterpret_cast<uint2*>(lo)[i] = make_uint2(l0, l1);
}

// ---------------------------------------------------------------------------
// V transpose + split: v[b*2048+s][h*64+d] -> vt[bh][d][s] (hi/lo bf16)
// ---------------------------------------------------------------------------
__global__ void vtrans_kernel(const float* __restrict__ v,
                              __nv_bfloat16* __restrict__ vth,
                              __nv_bfloat16* __restrict__ vtl)
{
    __shared__ float t[32][33];
    const int st = blockIdx.x, dt = blockIdx.y, bh = blockIdx.z;
    const int b = bh >> 4, h = bh & 15;
    const int lx = threadIdx.x & 31, ly = threadIdx.x >> 5;
#pragma unroll
    for (int i = 0; i < 4; i++) {
        int s = st * 32 + ly + 8 * i;
        t[ly + 8 * i][lx] = v[(size_t)(b * 2048 + s) * 1024 + h * 64 + dt * 32 + lx];
    }
    __syncthreads();
#pragma unroll
    for (int i = 0; i < 4; i++) {
        int d = dt * 32 + ly + 8 * i;
        float val = t[lx][ly + 8 * i];
        __nv_bfloat16 hi = __float2bfloat16(val);
        __nv_bfloat16 lo = __float2bfloat16(val - __bfloat162float(hi));
        size_t idx = ((size_t)bh * 64 + d) * 2048 + st * 32 + lx;
        vth[idx] = hi;
        vtl[idx] = lo;
    }
}

// ---------------------------------------------------------------------------
// RoPE cos/sin table
// ---------------------------------------------------------------------------
__global__ void rope_table_kernel()
{
    int idx = blockIdx.x * 256 + threadIdx.x;   // 65536
    int s = idx >> 5, i = idx & 31;
    double inv = exp(-((double)(2 * i) / 64.0) * log(10000.0));
    float  angf = (float)s * (float)inv;
    double ang  = (double)angf;
    g_cos[idx] = (float)cos(ang);
    g_sin[idx] = (float)sin(ang);
}

// ---------------------------------------------------------------------------
// bf16 mma.sync GEMM, fused 3-term fp32 emulation, single-sync 3-stage ring.
// Loop order per step: wait(keep 1 in flight) -> sync -> issue(s+2) -> compute.
// Safety: at the sync all warps finished step s-1, so buf (s+2)%3 (read at
// s-1) is reusable; each thread waited its own groups before the sync, so
// buf s%3 is visible to all.
// ---------------------------------------------------------------------------
constexpr int GEMM_SMEM = 98304;   // 3 stages * 32KB

__global__ void __launch_bounds__(256, 2)
gemm_bf3(const __nv_bfloat16* __restrict__ Ah, const __nv_bfloat16* __restrict__ Al,
         const __nv_bfloat16* __restrict__ Wh, const __nv_bfloat16* __restrict__ Wl,
         float* __restrict__ Df, __nv_bfloat16* __restrict__ Dh,
         __nv_bfloat16* __restrict__ Dl, int fused)
{
    extern __shared__ char smem[];
    const uint32_t sb = smem_to_u32(smem);
    const int tid = threadIdx.x, lane = tid & 31, wid = tid >> 5;
    const int z = blockIdx.z;
    const __nv_bfloat16* WhZ = Wh + (size_t)z * W_STRIDE;
    const __nv_bfloat16* WlZ = Wl + (size_t)z * W_STRIDE;
    const int m0 = blockIdx.y * 128, n0 = blockIdx.x * 128;
    const int wm = (wid >> 1) * 32, wn = (wid & 1) * 64;

    auto issue_loads = [&](int s, int buf) {
        const int k0 = s * 32;
        uint32_t base = sb + buf * 32768u;
#pragma unroll
        for (int i = 0; i < 2; i++) {
            int idx = tid + 256 * i;
            int row = idx >> 2, ch = idx & 3;
            uint32_t sw = (uint32_t)row * 64 + ((uint32_t)(ch ^ ((row >> 1) & 3)) << 4);
            size_t ga = (size_t)(m0 + row) * 1024 + k0 + ch * 8;
            size_t gb = (size_t)(n0 + row) * 1024 + k0 + ch * 8;
            cp_async16(base + sw,          Ah  + ga);
            cp_async16(base + 8192 + sw,   Al  + ga);
            cp_async16(base + 16384 + sw,  WhZ + gb);
            cp_async16(base + 24576 + sw,  WlZ + gb);
        }
        cp_commit();
    };

    float c[2][8][4];
#pragma unroll
    for (int i = 0; i < 2; i++)
#pragma unroll
        for (int j = 0; j < 8; j++)
#pragma unroll
            for (int q = 0; q < 4; q++) c[i][j][q] = 0.f;

    const int mrowA0 = wm + ((lane >> 3) & 1) * 8 + (lane & 7);
    const int kcA    = (lane >> 4) & 1;
    const int nrowB0 = wn + ((lane >> 4) & 1) * 8 + (lane & 7);
    const int kcB    = (lane >> 3) & 1;

    issue_loads(0, 0);
    issue_loads(1, 1);

    for (int s = 0; s < 32; s++) {
        const int buf = s % 3;
        if (s + 1 < 32) cp_wait<1>(); else cp_wait<0>();
        __syncthreads();
        if (s + 2 < 32) issue_loads(s + 2, (s + 2) % 3);

        const uint32_t abase = sb + buf * 32768u;
        const uint32_t bbase = abase + 16384u;
#pragma unroll
        for (int kc2 = 0; kc2 < 2; kc2++) {
            uint32_t ah[2][4], al[2][4];
#pragma unroll
            for (int i = 0; i < 2; i++) {
                int mr = mrowA0 + 16 * i;
                int unit = (kc2 << 1) | kcA;
                uint32_t addr = abase + mr * 64 +
                    ((uint32_t)(unit ^ ((mr >> 1) & 3)) << 4);
                ldmx4(ah[i], addr);
                ldmx4(al[i], addr + 8192);
            }
#pragma unroll
            for (int j = 0; j < 4; j++) {
                int nr = nrowB0 + 16 * j;
                int unit = (kc2 << 1) | kcB;
                uint32_t baddr = bbase + nr * 64 +
                    ((uint32_t)(unit ^ ((nr >> 1) & 3)) << 4);
                uint32_t bh[4], bl[4];
                ldmx4(bh, baddr);
                ldmx4(bl, baddr + 8192);
#pragma unroll
                for (int i = 0; i < 2; i++) {
                    mma_bf16(c[i][2 * j],     ah[i], bh[0], bh[1]);
                    mma_bf16(c[i][2 * j + 1], ah[i], bh[2], bh[3]);
                    mma_bf16(c[i][2 * j],     al[i], bh[0], bh[1]);
                    mma_bf16(c[i][2 * j + 1], al[i], bh[2], bh[3]);
                    mma_bf16(c[i][2 * j],     ah[i], bl[0], bl[1]);
                    mma_bf16(c[i][2 * j + 1], ah[i], bl[2], bl[3]);
                }
            }
        }
    }

    const int g = lane >> 2, tig = lane & 3;

    if (fused && z < 2) {
        __nv_bfloat16* DhZ = Dh + (size_t)z * QKV_STRIDE;
        __nv_bfloat16* DlZ = Dl + (size_t)z * QKV_STRIDE;
#pragma unroll
        for (int i = 0; i < 2; i++) {
            int mrow = m0 + wm + 16 * i + g;
            int s0 = mrow & 2047, s1 = (mrow + 8) & 2047;
#pragma unroll
            for (int nt = 0; nt < 8; nt++) {
                int col = n0 + wn + nt * 8 + tig * 2;
                int fi = (col & 63) >> 1;
                float cv0 = g_cos[s0 * 32 + fi], sv0 = g_sin[s0 * 32 + fi];
                float cv1 = g_cos[s1 * 32 + fi], sv1 = g_sin[s1 * 32 + fi];
                float r0 = c[i][nt][0] * cv0 - c[i][nt][1] * sv0;
                float r1 = c[i][nt][0] * sv0 + c[i][nt][1] * cv0;
                float r2 = c[i][nt][2] * cv1 - c[i][nt][3] * sv1;
                float r3 = c[i][nt][2] * sv1 + c[i][nt][3] * cv1;
                uint32_t h, l;
                size_t idx0 = (size_t)mrow * 1024 + col;
                split2pack(r0, r1, h, l);
                *reinterpret_cast<uint32_t*>(DhZ + idx0) = h;
                *reinterpret_cast<uint32_t*>(DlZ + idx0) = l;
                size_t idx1 = idx0 + (size_t)8 * 1024;
                split2pack(r2, r3, h, l);
                *reinterpret_cast<uint32_t*>(DhZ + idx1) = h;
                *reinterpret_cast<uint32_t*>(DlZ + idx1) = l;
            }
        }
    } else {
#pragma unroll
        for (int i = 0; i < 2; i++) {
            int mrow = m0 + wm + 16 * i + g;
#pragma unroll
            for (int nt = 0; nt < 8; nt++) {
                int col = n0 + wn + nt * 8 + tig * 2;
                float* p = Df + (size_t)mrow * 1024 + col;
                *reinterpret_cast<float2*>(p) = make_float2(c[i][nt][0], c[i][nt][1]);
                *reinterpret_cast<float2*>(p + 8 * 1024) = make_float2(c[i][nt][2], c[i][nt][3]);
            }
        }
    }
}

// ---------------------------------------------------------------------------
// Tensor-core causal flash attention, double-buffered K/V, 2 CTAs/SM,
// single barrier per kv-tile (wait -> sync -> issue-next -> compute).
// ---------------------------------------------------------------------------
constexpr int ATT_SMEM = 98304;
constexpr uint32_t QH_O = 0, QL_O = 16384, KV_O = 32768;

__global__ void __launch_bounds__(256, 2)
fattn_tc(const __nv_bfloat16* __restrict__ QKh,
         const __nv_bfloat16* __restrict__ QKl,
         const __nv_bfloat16* __restrict__ Vth,
         const __nv_bfloat16* __restrict__ Vtl,
         __nv_bfloat16* __restrict__ Oh, __nv_bfloat16* __restrict__ Ol)
{
    extern __shared__ char smem[];
    const uint32_t sb = smem_to_u32(smem);
    const int tid = threadIdx.x, lane = tid & 31, w = tid >> 5;
    const int qt = (int)gridDim.x - 1 - (int)blockIdx.x;
    const int bh = blockIdx.y;
    const int b = bh >> 4, h = bh & 15;
    const int q0 = qt * 128;
    const int njk = 2 * qt + 2;

    auto issue_kv = [&](int jk, int buf) {
        uint32_t base = sb + KV_O + buf * 32768u;
#pragma unroll
        for (int i = 0; i < 2; i++) {
            int idx = tid + 256 * i;
            int r = idx >> 3, ch = idx & 7;
            uint32_t sw = r * 128 + ((ch ^ (r & 7)) << 4);
            size_t gk = QKV_STRIDE + (size_t)(b * 2048 + jk * 64 + r) * 1024 + h * 64 + ch * 8;
            cp_async16(base + sw,         QKh + gk);
            cp_async16(base + 8192 + sw,  QKl + gk);
            size_t gv = ((size_t)bh * 64 + r) * 2048 + jk * 64 + ch * 8;
            cp_async16(base + 16384 + sw, Vth + gv);
            cp_async16(base + 24576 + sw, Vtl + gv);
        }
        cp_commit();
    };

#pragma unroll
    for (int i = 0; i < 4; i++) {
        int idx = tid + 256 * i;
        int r = idx >> 3, ch = idx & 7;
        size_t gq = (size_t)(b * 2048 + q0 + r) * 1024 + h * 64 + ch * 8;
        uint32_t sw = r * 128 + ((ch ^ (r & 7)) << 4);
        cp_async16(sb + QH_O + sw, QKh + gq);
        cp_async16(sb + QL_O + sw, QKl + gq);
    }
    cp_commit();
    issue_kv(0, 0);

    float o[8][4];
#pragma unroll
    for (int nt = 0; nt < 8; nt++)
#pragma unroll
        for (int q = 0; q < 4; q++) o[nt][q] = 0.f;
    float m0 = -1e30f, m1 = -1e30f, l0 = 0.f, l1 = 0.f;

    const int g_  = lane >> 2, tig = lane & 3;
    const int mrA = w * 16 + ((lane >> 3) & 1) * 8 + (lane & 7);
    const int kcA = (lane >> 4) & 1;
    const int nrB = ((lane >> 4) & 1) * 8 + (lane & 7);
    const int kcB = (lane >> 3) & 1;
    const int row0 = q0 + w * 16 + g_;

    for (int jk = 0; jk < njk; jk++) {
        const int buf = jk & 1;
        cp_wait<0>();
        __syncthreads();
        if (jk + 1 < njk) issue_kv(jk + 1, buf ^ 1);

        const uint32_t kbase = sb + KV_O + buf * 32768u;
        const uint32_t vbase = kbase + 16384u;

        float c[8][4];
#pragma unroll
        for (int nt = 0; nt < 8; nt++)
#pragma unroll
            for (int q = 0; q < 4; q++) c[nt][q] = 0.f;

#pragma unroll
        for (int k16 = 0; k16 < 4; k16++) {
            uint32_t ah[4], al[4];
            uint32_t aaddr = sb + QH_O + mrA * 128 +
                ((((k16 << 1) | kcA) ^ (mrA & 7)) << 4);
            ldmx4(ah, aaddr);
            ldmx4(al, aaddr + (QL_O - QH_O));
#pragma unroll
            for (int j = 0; j < 4; j++) {
                int nr = 16 * j + nrB;
                uint32_t baddr = kbase + nr * 128 +
                    ((((k16 << 1) | kcB) ^ (nr & 7)) << 4);
                uint32_t bhh[4], bll[4];
                ldmx4(bhh, baddr);
                ldmx4(bll, baddr + 8192);
                mma_bf16(c[2 * j],     ah, bhh[0], bhh[1]);
                mma_bf16(c[2 * j + 1], ah, bhh[2], bhh[3]);
                mma_bf16(c[2 * j],     al, bhh[0], bhh[1]);
                mma_bf16(c[2 * j + 1], al, bhh[2], bhh[3]);
                mma_bf16(c[2 * j],     ah, bll[0], bll[1]);
                mma_bf16(c[2 * j + 1], ah, bll[2], bll[3]);
            }
        }

#pragma unroll
        for (int nt = 0; nt < 8; nt++)
#pragma unroll
            for (int q = 0; q < 4; q++) c[nt][q] *= 0.125f;

        if (jk >= 2 * qt) {
#pragma unroll
            for (int nt = 0; nt < 8; nt++) {
                int colg = jk * 64 + 8 * nt + 2 * tig;
                if (colg     > row0)     c[nt][0] = -1e30f;
                if (colg + 1 > row0)     c[nt][1] = -1e30f;
                if (colg     > row0 + 8) c[nt][2] = -1e30f;
                if (colg + 1 > row0 + 8) c[nt][3] = -1e30f;
            }
        }

        float rm0 = -1e30f, rm1 = -1e30f;
#pragma unroll
        for (int nt = 0; nt < 8; nt++) {
            rm0 = fmaxf(rm0, fmaxf(c[nt][0], c[nt][1]));
            rm1 = fmaxf(rm1, fmaxf(c[nt][2], c[nt][3]));
        }
        rm0 = fmaxf(rm0, __shfl_xor_sync(0xffffffffu, rm0, 1));
        rm0 = fmaxf(rm0, __shfl_xor_sync(0xffffffffu, rm0, 2));
        rm1 = fmaxf(rm1, __shfl_xor_sync(0xffffffffu, rm1, 1));
        rm1 = fmaxf(rm1, __shfl_xor_sync(0xffffffffu, rm1, 2));

        float mn0 = fmaxf(m0, rm0), mn1 = fmaxf(m1, rm1);
        float a0 = __expf(m0 - mn0), a1 = __expf(m1 - mn1);
        m0 = mn0; m1 = mn1;

        float rs0 = 0.f, rs1 = 0.f;
#pragma unroll
        for (int nt = 0; nt < 8; nt++) {
            c[nt][0] = __expf(c[nt][0] - mn0);
            c[nt][1] = __expf(c[nt][1] - mn0);
            c[nt][2] = __expf(c[nt][2] - mn1);
            c[nt][3] = __expf(c[nt][3] - mn1);
            rs0 += c[nt][0] + c[nt][1];
            rs1 += c[nt][2] + c[nt][3];
        }
        rs0 += __shfl_xor_sync(0xffffffffu, rs0, 1);
        rs0 += __shfl_xor_sync(0xffffffffu, rs0, 2);
        rs1 += __shfl_xor_sync(0xffffffffu, rs1, 1);
        rs1 += __shfl_xor_sync(0xffffffffu, rs1, 2);
        l0 = l0 * a0 + rs0;
        l1 = l1 * a1 + rs1;
#pragma unroll
        for (int nt = 0; nt < 8; nt++) {
            o[nt][0] *= a0; o[nt][1] *= a0;
            o[nt][2] *= a1; o[nt][3] *= a1;
        }

#pragma unroll
        for (int k16 = 0; k16 < 4; k16++) {
            uint32_t aph[4], apl[4];
            split2pack(c[2 * k16][0],     c[2 * k16][1],     aph[0], apl[0]);
            split2pack(c[2 * k16][2],     c[2 * k16][3],     aph[1], apl[1]);
            split2pack(c[2 * k16 + 1][0], c[2 * k16 + 1][1], aph[2], apl[2]);
            split2pack(c[2 * k16 + 1][2], c[2 * k16 + 1][3], aph[3], apl[3]);
#pragma unroll
            for (int j = 0; j < 4; j++) {
                int nr = 16 * j + nrB;
                uint32_t baddr = vbase + nr * 128 +
                    ((((k16 << 1) | kcB) ^ (nr & 7)) << 4);
                uint32_t vhh[4], vll[4];
                ldmx4(vhh, baddr);
                ldmx4(vll, baddr + 8192);
                mma_bf16(o[2 * j],     aph, vhh[0], vhh[1]);
                mma_bf16(o[2 * j + 1], aph, vhh[2], vhh[3]);
                mma_bf16(o[2 * j],     apl, vhh[0], vhh[1]);
                mma_bf16(o[2 * j + 1], apl, vhh[2], vhh[3]);
                mma_bf16(o[2 * j],     aph, vll[0], vll[1]);
                mma_bf16(o[2 * j + 1], aph, vll[2], vll[3]);
            }
        }
    }

    float inv0 = 1.0f / l0, inv1 = 1.0f / l1;
    size_t base0 = (size_t)(b * 2048 + row0) * 1024 + h * 64 + 2 * tig;
    size_t base1 = base0 + (size_t)8 * 1024;
#pragma unroll
    for (int nt = 0; nt < 8; nt++) {
        uint32_t hh, ll;
        split2pack(o[nt][0] * inv0, o[nt][1] * inv0, hh, ll);
        *reinterpret_cast<uint32_t*>(Oh + base0 + 8 * nt) = hh;
        *reinterpret_cast<uint32_t*>(Ol + base0 + 8 * nt) = ll;
        split2pack(o[nt][2] * inv1, o[nt][3] * inv1, hh, ll);
        *reinterpret_cast<uint32_t*>(Oh + base1 + 8 * nt) = hh;
        *reinterpret_cast<uint32_t*>(Ol + base1 + 8 * nt) = ll;
    }
}

// ---------------------------------------------------------------------------
extern "C" void kernel_launch(void* const* d_in, const int* in_sizes, int n_in,
                              void* d_out, int out_size)
{
    (void)in_sizes; (void)n_in; (void)out_size;
    const float* x  = (const float*)d_in[0];
    const float* wq = (const float*)d_in[1];
    const float* wk = (const float*)d_in[2];
    const float* wv = (const float*)d_in[3];
    const float* wo = (const float*)d_in[4];
    float* out = (float*)d_out;

    float* pv;
    __nv_bfloat16 *pah, *pal, *pwh, *pwl, *pqkh, *pqkl, *pvth, *pvtl;
    cudaGetSymbolAddress((void**)&pv,   g_v);
    cudaGetSymbolAddress((void**)&pah,  g_ah);
    cudaGetSymbolAddress((void**)&pal,  g_al);
    cudaGetSymbolAddress((void**)&pwh,  g_wh);
    cudaGetSymbolAddress((void**)&pwl,  g_wl);
    cudaGetSymbolAddress((void**)&pqkh, g_qkh);
    cudaGetSymbolAddress((void**)&pqkl, g_qkl);
    cudaGetSymbolAddress((void**)&pvth, g_vth);
    cudaGetSymbolAddress((void**)&pvtl, g_vtl);

    cudaFuncSetAttribute(gemm_bf3, cudaFuncAttributeMaxDynamicSharedMemorySize, GEMM_SMEM);
    cudaFuncSetAttribute(fattn_tc, cudaFuncAttributeMaxDynamicSharedMemorySize, ATT_SMEM);

    const int n4x = M_TOT * D_ / 4;      // 2097152

    rope_table_kernel<<<(S_ * 32) / 256, 256>>>();
    split_kernel<<<n4x / 256, 256>>>(x, pah, pal, n4x);
    wsplit_kernel<<<(int)(4 * W_STRIDE / 4) / 256, 256>>>(wq, wk, wv, wo, pwh, pwl);

    // Fused QKV projection: z=0,1 -> RoPE'd bf16 q/k; z=2 -> fp32 v
    gemm_bf3<<<dim3(8, 64, 3), 256, GEMM_SMEM>>>(pah, pal, pwh, pwl,
                                                 pv, pqkh, pqkl, 1);

    vtrans_kernel<<<dim3(64, 2, 64), 256>>>(pv, pvth, pvtl);

    // Attention: writes bf16 hi/lo splits straight into pah/pal
    fattn_tc<<<dim3(16, 64), 256, ATT_SMEM>>>(pqkh, pqkl, pvth, pvtl, pah, pal);

    // Output projection (wo = weight index 3), fp32 out
    gemm_bf3<<<dim3(8, 64, 1), 256, GEMM_SMEM>>>(pah, pal,
        pwh + 3 * W_STRIDE, pwl + 3 * W_STRIDE, out, nullptr, nullptr, 0);
}